// round 12
// baseline (speedup 1.0000x reference)
#include <cuda_runtime.h>
#include <cuda_bf16.h>
#include <math.h>
#include <stdint.h>

#define B_SZ   32
#define S_LEN  577
#define E_DIM  768
#define NH     12
#define DH     64
#define BH     (B_SZ * NH)         // 384
#define M_ROWS (B_SZ * S_LEN)      // 18464
#define QKV_F  (3 * E_DIM)         // 2304
#define SPAD   640
#define HSTRIDE ((size_t)B_SZ * NH * S_LEN * DH)

// Scratch (device globals; allocation-free per harness rules)
__device__ float g_qkv[(size_t)3 * B_SZ * NH * S_LEN * DH];  // [t][b][h][s][d] (t<2 used)
__device__ __nv_bfloat16 g_ahi[(size_t)M_ROWS * E_DIM];
__device__ __nv_bfloat16 g_alo[(size_t)M_ROWS * E_DIM];
__device__ __nv_bfloat16 g_bhi[(size_t)QKV_F * E_DIM];
__device__ __nv_bfloat16 g_blo[(size_t)QKV_F * E_DIM];
__device__ __nv_bfloat16 g_phi[(size_t)E_DIM * E_DIM];
__device__ __nv_bfloat16 g_plo[(size_t)E_DIM * E_DIM];
// flash operands
__device__ __nv_bfloat16 g_qhi[(size_t)BH * S_LEN * DH];
__device__ __nv_bfloat16 g_qlo[(size_t)BH * S_LEN * DH];
__device__ __nv_bfloat16 g_khi[(size_t)BH * S_LEN * DH];
__device__ __nv_bfloat16 g_klo[(size_t)BH * S_LEN * DH];
__device__ __nv_bfloat16 g_vthi[(size_t)BH * DH * SPAD];     // [bh][d][s]
__device__ __nv_bfloat16 g_vtlo[(size_t)BH * DH * SPAD];

__device__ __forceinline__ uint32_t smem_to_u32(const void* p) {
    uint32_t a;
    asm("{ .reg .u64 t; cvta.to.shared.u64 t, %1; cvt.u32.u64 %0, t; }" : "=r"(a) : "l"(p));
    return a;
}

// ---- mma.sync helpers ----
#define LDSM4(r, addr)                                                         \
    asm volatile("ldmatrix.sync.aligned.m8n8.x4.shared.b16 {%0,%1,%2,%3}, [%4];" \
        : "=r"((r)[0]), "=r"((r)[1]), "=r"((r)[2]), "=r"((r)[3]) : "r"(addr))

#define MMA16816(d, a, b0, b1)                                                 \
    asm volatile("mma.sync.aligned.m16n8k16.row.col.f32.bf16.bf16.f32 "        \
        "{%0,%1,%2,%3}, {%4,%5,%6,%7}, {%8,%9}, {%0,%1,%2,%3};"                \
        : "+f"((d)[0]), "+f"((d)[1]), "+f"((d)[2]), "+f"((d)[3])               \
        : "r"((a)[0]), "r"((a)[1]), "r"((a)[2]), "r"((a)[3]), "r"(b0), "r"(b1))

// 16B-chunk swizzles
#define CHUNK_OFF(row, c) (((row) << 6) + ((((c) ^ (((row) >> 1) & 3))) << 4)) // [r][32bf16]
#define CH8(row, c)       (((row) << 7) + ((((c) ^ ((row) & 7))) << 4))        // [r][64bf16]

__device__ __forceinline__ uint32_t pk2bf(float f0, float f1) {
    __nv_bfloat162 h = __floats2bfloat162_rn(f0, f1);
    return *(uint32_t*)&h;
}

// ======================= bf16 hi/lo split (GEMM inputs) =====================
__global__ __launch_bounds__(256) void split_bf16(const float4* __restrict__ src,
                                                  uint2* __restrict__ hi,
                                                  uint2* __restrict__ lo, int n4)
{
    int i = blockIdx.x * blockDim.x + threadIdx.x;
    if (i >= n4) return;
    float4 v = src[i];
    __nv_bfloat16 h0 = __float2bfloat16(v.x), h1 = __float2bfloat16(v.y);
    __nv_bfloat16 h2 = __float2bfloat16(v.z), h3 = __float2bfloat16(v.w);
    __nv_bfloat16 l0 = __float2bfloat16(v.x - __bfloat162float(h0));
    __nv_bfloat16 l1 = __float2bfloat16(v.y - __bfloat162float(h1));
    __nv_bfloat16 l2 = __float2bfloat16(v.z - __bfloat162float(h2));
    __nv_bfloat16 l3 = __float2bfloat16(v.w - __bfloat162float(h3));
    uint2 hv, lv;
    hv.x = ((uint32_t)__bfloat16_as_ushort(h1) << 16) | __bfloat16_as_ushort(h0);
    hv.y = ((uint32_t)__bfloat16_as_ushort(h3) << 16) | __bfloat16_as_ushort(h2);
    lv.x = ((uint32_t)__bfloat16_as_ushort(l1) << 16) | __bfloat16_as_ushort(l0);
    lv.y = ((uint32_t)__bfloat16_as_ushort(l3) << 16) | __bfloat16_as_ushort(l2);
    hi[i] = hv;
    lo[i] = lv;
}

// ======================= HMMA GEMM (bf16x3, cp.async 3-stage, 2 CTA/SM) =====
#define GEMM_STAGE 32768
#define GEMM_SMEM  (3 * GEMM_STAGE)

template<bool QKV>
__global__ __launch_bounds__(256, 2) void mma_gemm(float* __restrict__ C,
                                                   const __nv_bfloat16* __restrict__ Bhi,
                                                   const __nv_bfloat16* __restrict__ Blo)
{
    extern __shared__ char sm[];
    const int tid  = threadIdx.x;
    const int lane = tid & 31;
    const int wid  = tid >> 5;
    const int wm   = wid & 3;
    const int wn   = wid >> 2;
    const int row0 = blockIdx.y * 128;
    const int col0 = blockIdx.x * 128;
    const uint32_t smem = smem_to_u32(sm);

    const int lr = tid >> 2;
    const int lc = tid & 3;

    const int arow[2] = { wm * 32 + 0 * 16 + (lane & 7) + ((lane >> 3) & 1) * 8,
                          wm * 32 + 1 * 16 + (lane & 7) + ((lane >> 3) & 1) * 8 };
    const int achk = lane >> 4;
    const int brow[4] = { wn * 64 + 0 * 16 + (lane & 7) + (lane >> 4) * 8,
                          wn * 64 + 1 * 16 + (lane & 7) + (lane >> 4) * 8,
                          wn * 64 + 2 * 16 + (lane & 7) + (lane >> 4) * 8,
                          wn * 64 + 3 * 16 + (lane & 7) + (lane >> 4) * 8 };
    const int bchk = (lane >> 3) & 1;

#define ISSUE(s_)                                                              \
    {                                                                          \
        uint32_t sb_ = smem + ((s_) % 3) * GEMM_STAGE;                         \
        int k0_ = (s_) * 32;                                                   \
        _Pragma("unroll")                                                      \
        for (int p = 0; p < 2; p++) {                                          \
            int r = lr + p * 64;                                               \
            int rA = row0 + r;                                                 \
            uint32_t szA = (rA < M_ROWS) ? 16u : 0u;                           \
            size_t offA = (size_t)(rA < M_ROWS ? rA : 0) * E_DIM + k0_ + lc * 8; \
            size_t offB = (size_t)(col0 + r) * E_DIM + k0_ + lc * 8;           \
            uint32_t co = CHUNK_OFF(r, lc);                                    \
            asm volatile("cp.async.cg.shared.global [%0], [%1], 16, %2;"       \
                :: "r"(sb_ + co), "l"(g_ahi + offA), "r"(szA));                \
            asm volatile("cp.async.cg.shared.global [%0], [%1], 16, %2;"       \
                :: "r"(sb_ + 8192 + co), "l"(g_alo + offA), "r"(szA));         \
            asm volatile("cp.async.cg.shared.global [%0], [%1], 16;"           \
                :: "r"(sb_ + 16384 + co), "l"(Bhi + offB));                    \
            asm volatile("cp.async.cg.shared.global [%0], [%1], 16;"           \
                :: "r"(sb_ + 24576 + co), "l"(Blo + offB));                    \
        }                                                                      \
        asm volatile("cp.async.commit_group;");                                \
    }

    ISSUE(0)
    ISSUE(1)

    float acc[2][8][4] = {};

    for (int s = 0; s < 24; s++) {
        if (s + 1 < 24) asm volatile("cp.async.wait_group 1;");
        else            asm volatile("cp.async.wait_group 0;");
        __syncthreads();   // all warps past compute(s-1); stage s ready
        if (s + 2 < 24) ISSUE(s + 2)   // overwrites buffer (s-1)%3: safe after barrier

        const uint32_t sb = smem + (s % 3) * GEMM_STAGE;
#pragma unroll
        for (int ks = 0; ks < 2; ks++) {
            uint32_t ah[2][4], al[2][4];
#pragma unroll
            for (int i = 0; i < 2; i++) {
                uint32_t adr = sb + CHUNK_OFF(arow[i], ks * 2 + achk);
                LDSM4(ah[i], adr);
                LDSM4(al[i], adr + 8192);
            }
            uint32_t bh[4][4], bl[4][4];
#pragma unroll
            for (int g = 0; g < 4; g++) {
                uint32_t adr = sb + 16384 + CHUNK_OFF(brow[g], ks * 2 + bchk);
                LDSM4(bh[g], adr);
                LDSM4(bl[g], adr + 8192);
            }
#pragma unroll
            for (int i = 0; i < 2; i++)
#pragma unroll
                for (int g = 0; g < 4; g++)
#pragma unroll
                    for (int hh = 0; hh < 2; hh++) {
                        const int j = g * 2 + hh;
                        MMA16816(acc[i][j], ah[i], bh[g][hh*2], bh[g][hh*2+1]);
                        MMA16816(acc[i][j], ah[i], bl[g][hh*2], bl[g][hh*2+1]);
                        MMA16816(acc[i][j], al[i], bh[g][hh*2], bh[g][hh*2+1]);
                    }
        }
    }
#undef ISSUE

#pragma unroll
    for (int i = 0; i < 2; i++)
#pragma unroll
        for (int half = 0; half < 2; half++) {
            int m = row0 + wm * 32 + i * 16 + (lane >> 2) + half * 8;
            if (m >= M_ROWS) continue;
            int bb = 0, sIdx = 0;
            if (QKV) { bb = m / S_LEN; sIdx = m - bb * S_LEN; }
#pragma unroll
            for (int j = 0; j < 8; j++) {
                int n = col0 + wn * 64 + j * 8 + (lane & 3) * 2;
                float2 v = make_float2(acc[i][j][half*2], acc[i][j][half*2+1]);
                if (QKV) {
                    int t = n / E_DIM, r = n - t * E_DIM;
                    int h = r >> 6, d = r & 63;
                    if (t < 2) {
                        *(float2*)&g_qkv[(size_t)t * HSTRIDE
                            + (((size_t)bb * NH + h) * S_LEN + sIdx) * DH + d] = v;
                    } else {
                        // V: write transposed bf16 hi/lo directly
                        __nv_bfloat16 vh0 = __float2bfloat16(v.x);
                        __nv_bfloat16 vh1 = __float2bfloat16(v.y);
                        __nv_bfloat16 vl0 = __float2bfloat16(v.x - __bfloat162float(vh0));
                        __nv_bfloat16 vl1 = __float2bfloat16(v.y - __bfloat162float(vh1));
                        size_t vb = (size_t)(bb * NH + h) * (DH * SPAD);
                        g_vthi[vb + (size_t)d * SPAD + sIdx]       = vh0;
                        g_vthi[vb + (size_t)(d + 1) * SPAD + sIdx] = vh1;
                        g_vtlo[vb + (size_t)d * SPAD + sIdx]       = vl0;
                        g_vtlo[vb + (size_t)(d + 1) * SPAD + sIdx] = vl1;
                    }
                } else {
                    *(float2*)&C[(size_t)m * E_DIM + n] = v;
                }
            }
        }
}

// ======================= convert: rope (table) + split of q,k ===============
__global__ __launch_bounds__(256) void convert_rope_split()
{
    const int bh    = blockIdx.y;
    const int chunk = blockIdx.x;
    const int s0    = chunk * 64;
    const int tid   = threadIdx.x;
    const int wid   = tid >> 5, lane = tid & 31;
    const unsigned full = 0xffffffffu;

    __shared__ float ct[24][16], st[24][16];
    for (int e = tid; e < 384; e += 256) {
        int v = e >> 4, f = e & 15;
        float dv = expf(-(float)(2 * f) * (9.210340371976184f / 32.0f));
        float a  = (float)v * (1.0f / 23.00000001f) * dv;
        ct[v][f] = cosf(a);
        st[v][f] = sinf(a);
    }
    __syncthreads();

    const int fi = lane >> 1;

#pragma unroll
    for (int t = 0; t < 2; t++) {
        __nv_bfloat16* dhi = t ? g_khi : g_qhi;
        __nv_bfloat16* dlo = t ? g_klo : g_qlo;
#pragma unroll
        for (int ps = 0; ps < 8; ps++) {
            int s = s0 + ps * 8 + wid;
            float v0 = 0.f, v1 = 0.f;
            bool valid = (s < S_LEN);
            if (valid) {
                const float* base = g_qkv + (size_t)t * HSTRIDE
                                  + ((size_t)bh * S_LEN + s) * DH;
                v0 = base[lane];
                v1 = base[lane + 32];
            }
            float p0 = __shfl_sync(full, v0, (lane + 31) & 31);
            float p1 = __shfl_sync(full, v1, (lane + 31) & 31);
            if (valid && s > 0) {
                int p  = s - 1;
                int px = p % 24, py = p / 24;
                v0 = v0 * ct[px][fi] + p0 * st[px][fi];
                v1 = v1 * ct[py][fi] + p1 * st[py][fi];
            }
            if (valid) {
                size_t off = ((size_t)bh * S_LEN + s) * DH;
                __nv_bfloat16 h0 = __float2bfloat16(v0);
                __nv_bfloat16 h1 = __float2bfloat16(v1);
                dhi[off + lane]      = h0;
                dhi[off + lane + 32] = h1;
                dlo[off + lane]      = __float2bfloat16(v0 - __bfloat162float(h0));
                dlo[off + lane + 32] = __float2bfloat16(v1 - __bfloat162float(h1));
            }
        }
    }

    // zero V pad region s in [S_LEN, SPAD) so flash PV sees exact zeros
    if (chunk == 9) {
        const int padN = SPAD - S_LEN;   // 63
        for (int idx = tid; idx < DH * padN; idx += 256) {
            int d = idx / padN, s = S_LEN + idx % padN;
            size_t dst = (size_t)bh * (DH * SPAD) + (size_t)d * SPAD + s;
            g_vthi[dst] = __float2bfloat16(0.f);
            g_vtlo[dst] = __float2bfloat16(0.f);
        }
    }
}

// ======================= HMMA flash attention (64KB, 2 CTA/SM) ==============
#define FLASH_SMEM 65536

__global__ __launch_bounds__(256, 2) void flash_mma()
{
    extern __shared__ char sm[];
    const uint32_t smem = smem_to_u32(sm);

    const int bh  = blockIdx.y;
    const int i0  = blockIdx.x * 128;
    const int tid = threadIdx.x;
    const int lane = tid & 31, wid = tid >> 5;

#define KVBASE(t_) (smem + (((t_) & 1) ? 0u : 32768u))

#define ISSUE_KV(t_)                                                           \
    {                                                                          \
        uint32_t kb_ = KVBASE(t_);                                             \
        int j0_ = (t_) * 64;                                                   \
        _Pragma("unroll")                                                      \
        for (int it = 0; it < 2; it++) {                                       \
            int idx = tid + it * 256;                                          \
            int r = idx >> 3, c = idx & 7;                                     \
            int sj = j0_ + r;                                                  \
            uint32_t szK = (sj < S_LEN) ? 16u : 0u;                            \
            size_t koff = ((size_t)bh * S_LEN + (sj < S_LEN ? sj : 0)) * DH + c * 8; \
            size_t voff = (size_t)bh * (DH * SPAD) + (size_t)r * SPAD + j0_ + c * 8; \
            uint32_t co = CH8(r, c);                                           \
            asm volatile("cp.async.cg.shared.global [%0], [%1], 16, %2;"       \
                :: "r"(kb_ + co), "l"(g_khi + koff), "r"(szK));                \
            asm volatile("cp.async.cg.shared.global [%0], [%1], 16, %2;"       \
                :: "r"(kb_ + 8192 + co), "l"(g_klo + koff), "r"(szK));         \
            asm volatile("cp.async.cg.shared.global [%0], [%1], 16;"           \
                :: "r"(kb_ + 16384 + co), "l"(g_vthi + voff));                 \
            asm volatile("cp.async.cg.shared.global [%0], [%1], 16;"           \
                :: "r"(kb_ + 24576 + co), "l"(g_vtlo + voff));                 \
        }                                                                      \
        asm volatile("cp.async.commit_group;");                                \
    }

    ISSUE_KV(0)

#pragma unroll
    for (int it = 0; it < 4; it++) {
        int idx = tid + it * 256;
        int r = idx >> 3, c = idx & 7;
        int s = i0 + r;
        uint4 vh = make_uint4(0u,0u,0u,0u), vl = vh;
        if (s < S_LEN) {
            size_t off = ((size_t)bh * S_LEN + s) * DH + c * 8;
            vh = *(const uint4*)(g_qhi + off);
            vl = *(const uint4*)(g_qlo + off);
        }
        *(uint4*)(sm + CH8(r, c)) = vh;
        *(uint4*)(sm + 16384 + CH8(r, c)) = vl;
    }
    __syncthreads();

    uint32_t qhf[4][4], qlf[4][4];
    {
        const int ar = wid * 16 + (lane & 7) + ((lane >> 3) & 1) * 8;
        const int ac = lane >> 4;
#pragma unroll
        for (int kt = 0; kt < 4; kt++) {
            LDSM4(qhf[kt], smem + CH8(ar, kt * 2 + ac));
            LDSM4(qlf[kt], smem + 16384 + CH8(ar, kt * 2 + ac));
        }
    }
    __syncthreads();

    ISSUE_KV(1)

    float oacc[8][4] = {};
    float m0 = -1e30f, m1 = -1e30f, l0 = 0.f, l1 = 0.f;

    const int br = (lane & 7) + ((lane >> 4) << 3);
    const int bc = (lane >> 3) & 1;

    for (int t = 0; t < 10; t++) {
        const int j0 = t * 64;
        if (t < 8) asm volatile("cp.async.wait_group 1;");
        else       asm volatile("cp.async.wait_group 0;");
        __syncthreads();

        const uint32_t kvb  = KVBASE(t);
        const uint32_t kh32 = kvb,          kl32 = kvb + 8192;
        const uint32_t vh32 = kvb + 16384,  vl32 = kvb + 24576;

        float sacc[8][4] = {};
#pragma unroll
        for (int kt = 0; kt < 4; kt++) {
            uint32_t khf[4][4], klf[4][4];
#pragma unroll
            for (int g = 0; g < 4; g++) {
                uint32_t adr = CH8(g * 16 + br, kt * 2 + bc);
                LDSM4(khf[g], kh32 + adr);
                LDSM4(klf[g], kl32 + adr);
            }
#pragma unroll
            for (int g = 0; g < 4; g++)
#pragma unroll
                for (int hh = 0; hh < 2; hh++) {
                    const int j = g * 2 + hh;
                    MMA16816(sacc[j], qhf[kt], khf[g][hh*2], khf[g][hh*2+1]);
                    MMA16816(sacc[j], qhf[kt], klf[g][hh*2], klf[g][hh*2+1]);
                    MMA16816(sacc[j], qlf[kt], khf[g][hh*2], khf[g][hh*2+1]);
                }
        }

        float tm0 = -1e30f, tm1 = -1e30f;
#pragma unroll
        for (int nt = 0; nt < 8; nt++) {
            int jb = j0 + nt * 8 + (lane & 3) * 2;
            sacc[nt][0] = (jb     < S_LEN) ? sacc[nt][0] * 0.125f : -1e30f;
            sacc[nt][1] = (jb + 1 < S_LEN) ? sacc[nt][1] * 0.125f : -1e30f;
            sacc[nt][2] = (jb     < S_LEN) ? sacc[nt][2] * 0.125f : -1e30f;
            sacc[nt][3] = (jb + 1 < S_LEN) ? sacc[nt][3] * 0.125f : -1e30f;
            tm0 = fmaxf(tm0, fmaxf(sacc[nt][0], sacc[nt][1]));
            tm1 = fmaxf(tm1, fmaxf(sacc[nt][2], sacc[nt][3]));
        }
        tm0 = fmaxf(tm0, __shfl_xor_sync(0xffffffffu, tm0, 1));
        tm0 = fmaxf(tm0, __shfl_xor_sync(0xffffffffu, tm0, 2));
        tm1 = fmaxf(tm1, __shfl_xor_sync(0xffffffffu, tm1, 1));
        tm1 = fmaxf(tm1, __shfl_xor_sync(0xffffffffu, tm1, 2));
        float mn0 = fmaxf(m0, tm0), mn1 = fmaxf(m1, tm1);
        float f0 = __expf(m0 - mn0), f1 = __expf(m1 - mn1);
        m0 = mn0; m1 = mn1;

        float rs0 = 0.f, rs1 = 0.f;
#pragma unroll
        for (int nt = 0; nt < 8; nt++) {
            sacc[nt][0] = __expf(sacc[nt][0] - mn0);
            sacc[nt][1] = __expf(sacc[nt][1] - mn0);
            sacc[nt][2] = __expf(sacc[nt][2] - mn1);
            sacc[nt][3] = __expf(sacc[nt][3] - mn1);
            rs0 += sacc[nt][0] + sacc[nt][1];
            rs1 += sacc[nt][2] + sacc[nt][3];
        }
        rs0 += __shfl_xor_sync(0xffffffffu, rs0, 1);
        rs0 += __shfl_xor_sync(0xffffffffu, rs0, 2);
        rs1 += __shfl_xor_sync(0xffffffffu, rs1, 1);
        rs1 += __shfl_xor_sync(0xffffffffu, rs1, 2);
        l0 = l0 * f0 + rs0;
        l1 = l1 * f1 + rs1;

#pragma unroll
        for (int nt = 0; nt < 8; nt++) {
            oacc[nt][0] *= f0; oacc[nt][1] *= f0;
            oacc[nt][2] *= f1; oacc[nt][3] *= f1;
        }

        uint32_t pahi[4][4], palo[4][4];
#pragma unroll
        for (int kt = 0; kt < 4; kt++) {
            const int t0 = kt * 2, t1 = kt * 2 + 1;
            float v00 = sacc[t0][0], v01 = sacc[t0][1];
            float v02 = sacc[t0][2], v03 = sacc[t0][3];
            float v10 = sacc[t1][0], v11 = sacc[t1][1];
            float v12 = sacc[t1][2], v13 = sacc[t1][3];
            pahi[kt][0] = pk2bf(v00, v01);
            pahi[kt][1] = pk2bf(v02, v03);
            pahi[kt][2] = pk2bf(v10, v11);
            pahi[kt][3] = pk2bf(v12, v13);
            palo[kt][0] = pk2bf(v00 - __bfloat162float(__float2bfloat16(v00)),
                                v01 - __bfloat162float(__float2bfloat16(v01)));
            palo[kt][1] = pk2bf(v02 - __bfloat162float(__float2bfloat16(v02)),
                                v03 - __bfloat162float(__float2bfloat16(v03)));
            palo[kt][2] = pk2bf(v10 - __bfloat162float(__float2bfloat16(v10)),
                                v11 - __bfloat162float(__float2bfloat16(v11)));
            palo[kt][3] = pk2bf(v12 - __bfloat162float(__float2bfloat16(v12)),
                                v13 - __bfloat162float(__float2bfloat16(v13)));
        }

#pragma unroll
        for (int kt = 0; kt < 4; kt++) {
            uint32_t vhf[4][4], vlf[4][4];
#pragma unroll
            for (int g = 0; g < 4; g++) {
                uint32_t adr = CH8(g * 16 + br, kt * 2 + bc);
                LDSM4(vhf[g], vh32 + adr);
                LDSM4(vlf[g], vl32 + adr);
            }
#pragma unroll
            for (int g = 0; g < 4; g++)
#pragma unroll
                for (int hh = 0; hh < 2; hh++) {
                    const int j = g * 2 + hh;
                    MMA16816(oacc[j], pahi[kt], vhf[g][hh*2], vhf[g][hh*2+1]);
                    MMA16816(oacc[j], pahi[kt], vlf[g][hh*2], vlf[g][hh*2+1]);
                    MMA16816(oacc[j], palo[kt], vhf[g][hh*2], vhf[g][hh*2+1]);
                }
        }
        __syncthreads();
        if (t + 2 < 10) ISSUE_KV(t + 2)
    }
#undef ISSUE_KV
#undef KVBASE

    // epilogue: write ctx directly as bf16 hi/lo (input A of out-proj GEMM)
    const float inv0 = 1.f / l0, inv1 = 1.f / l1;
    const int b = bh / NH, h = bh % NH;
    const int r0 = i0 + wid * 16 + (lane >> 2);
    const int r1 = r0 + 8;
#pragma unroll
    for (int nt = 0; nt < 8; nt++) {
        int d = nt * 8 + (lane & 3) * 2;
        if (r0 < S_LEN) {
            float o0 = oacc[nt][0] * inv0, o1 = oacc[nt][1] * inv0;
            size_t off = ((size_t)b * S_LEN + r0) * E_DIM + h * DH + d;
            *(uint32_t*)&g_ahi[off] = pk2bf(o0, o1);
            *(uint32_t*)&g_alo[off] = pk2bf(o0 - __bfloat162float(__float2bfloat16(o0)),
                                            o1 - __bfloat162float(__float2bfloat16(o1)));
        }
        if (r1 < S_LEN) {
            float o2 = oacc[nt][2] * inv1, o3 = oacc[nt][3] * inv1;
            size_t off = ((size_t)b * S_LEN + r1) * E_DIM + h * DH + d;
            *(uint32_t*)&g_ahi[off] = pk2bf(o2, o3);
            *(uint32_t*)&g_alo[off] = pk2bf(o2 - __bfloat162float(__float2bfloat16(o2)),
                                            o3 - __bfloat162float(__float2bfloat16(o3)));
        }
    }
}

// ======================= launch =============================================
extern "C" void kernel_launch(void* const* d_in, const int* in_sizes, int n_in,
                              void* d_out, int out_size)
{
    (void)in_sizes; (void)n_in; (void)out_size;
    const float* x      = (const float*)d_in[0];
    const float* w_qkv  = (const float*)d_in[1];
    const float* w_proj = (const float*)d_in[2];
    float* out = (float*)d_out;

    void *ahi, *alo, *bhi, *blo, *phi, *plo;
    cudaGetSymbolAddress(&ahi, g_ahi);
    cudaGetSymbolAddress(&alo, g_alo);
    cudaGetSymbolAddress(&bhi, g_bhi);
    cudaGetSymbolAddress(&blo, g_blo);
    cudaGetSymbolAddress(&phi, g_phi);
    cudaGetSymbolAddress(&plo, g_plo);

    cudaFuncSetAttribute(mma_gemm<true>,  cudaFuncAttributeMaxDynamicSharedMemorySize, GEMM_SMEM);
    cudaFuncSetAttribute(mma_gemm<false>, cudaFuncAttributeMaxDynamicSharedMemorySize, GEMM_SMEM);
    cudaFuncSetAttribute(flash_mma, cudaFuncAttributeMaxDynamicSharedMemorySize, FLASH_SMEM);

    const int MT = (M_ROWS + 127) / 128;   // 145

    // 1) all input splits up front
    {
        int n4 = M_ROWS * E_DIM / 4;
        split_bf16<<<(n4 + 255) / 256, 256>>>((const float4*)x, (uint2*)ahi, (uint2*)alo, n4);
        int w4 = QKV_F * E_DIM / 4;
        split_bf16<<<(w4 + 255) / 256, 256>>>((const float4*)w_qkv, (uint2*)bhi, (uint2*)blo, w4);
        int p4 = E_DIM * E_DIM / 4;
        split_bf16<<<(p4 + 255) / 256, 256>>>((const float4*)w_proj, (uint2*)phi, (uint2*)plo, p4);
    }

    // 2) QKV projection -> q,k fp32 in g_qkv; V direct to bf16 hi/lo transposed
    mma_gemm<true><<<dim3(QKV_F / 128, MT), 256, GEMM_SMEM>>>(
        nullptr, (const __nv_bfloat16*)bhi, (const __nv_bfloat16*)blo);

    // 3) rope (table) + bf16 split of q,k; zero V pad
    convert_rope_split<<<dim3(10, BH), 256>>>();

    // 4) HMMA flash attention -> ctx written as bf16 hi/lo into g_ahi/g_alo
    flash_mma<<<dim3(5, BH), 256, FLASH_SMEM>>>();

    // 5) output projection
    mma_gemm<false><<<dim3(E_DIM / 128, MT), 256, GEMM_SMEM>>>(
        out, (const __nv_bfloat16*)phi, (const __nv_bfloat16*)plo);
}

// round 13
// speedup vs baseline: 1.3595x; 1.3595x over previous
#include <cuda_runtime.h>
#include <cuda_fp16.h>
#include <math.h>
#include <stdint.h>

#define B_SZ   32
#define S_LEN  577
#define E_DIM  768
#define NH     12
#define DH     64
#define BH     (B_SZ * NH)         // 384
#define M_ROWS (B_SZ * S_LEN)      // 18464
#define QKV_F  (3 * E_DIM)         // 2304
#define SPAD   640
#define HSTRIDE ((size_t)B_SZ * NH * S_LEN * DH)

// Scratch (device globals; allocation-free per harness rules)
__device__ float g_qkv[(size_t)3 * B_SZ * NH * S_LEN * DH];  // [t][b][h][s][d]
__device__ __half g_ahi[(size_t)M_ROWS * E_DIM];   // A hi (x, then ctx)
__device__ __half g_alo[(size_t)M_ROWS * E_DIM];   // A lo
__device__ __half g_bh [(size_t)QKV_F * E_DIM];    // w_qkv fp16
__device__ __half g_ph [(size_t)E_DIM * E_DIM];    // w_proj fp16
// flash operands
__device__ __half g_qhi[(size_t)BH * S_LEN * DH];
__device__ __half g_qlo[(size_t)BH * S_LEN * DH];
__device__ __half g_kh [(size_t)BH * S_LEN * DH];
__device__ __half g_vt [(size_t)BH * DH * SPAD];   // V^T fp16 [bh][d][s]

__device__ __forceinline__ uint32_t smem_to_u32(const void* p) {
    uint32_t a;
    asm("{ .reg .u64 t; cvta.to.shared.u64 t, %1; cvt.u32.u64 %0, t; }" : "=r"(a) : "l"(p));
    return a;
}

// ---- mma.sync helpers (fp16 in, fp32 accum) ----
#define LDSM4(r, addr)                                                         \
    asm volatile("ldmatrix.sync.aligned.m8n8.x4.shared.b16 {%0,%1,%2,%3}, [%4];" \
        : "=r"((r)[0]), "=r"((r)[1]), "=r"((r)[2]), "=r"((r)[3]) : "r"(addr))

#define MMA16816(d, a, b0, b1)                                                 \
    asm volatile("mma.sync.aligned.m16n8k16.row.col.f32.f16.f16.f32 "          \
        "{%0,%1,%2,%3}, {%4,%5,%6,%7}, {%8,%9}, {%0,%1,%2,%3};"                \
        : "+f"((d)[0]), "+f"((d)[1]), "+f"((d)[2]), "+f"((d)[3])               \
        : "r"((a)[0]), "r"((a)[1]), "r"((a)[2]), "r"((a)[3]), "r"(b0), "r"(b1))

// 16B-chunk swizzles
#define CHUNK_OFF(row, c) (((row) << 6) + ((((c) ^ (((row) >> 1) & 3))) << 4)) // [r][32 h16]
#define CH8(row, c)       (((row) << 7) + ((((c) ^ ((row) & 7))) << 4))        // [r][64 h16]

__device__ __forceinline__ uint32_t pk2h(float f0, float f1) {
    __half2 h = __floats2half2_rn(f0, f1);
    return *(uint32_t*)&h;
}

// ======================= fp16 splits ========================================
__global__ __launch_bounds__(256) void split2_h(const float4* __restrict__ src,
                                                uint2* __restrict__ hi,
                                                uint2* __restrict__ lo, int n4)
{
    int i = blockIdx.x * blockDim.x + threadIdx.x;
    if (i >= n4) return;
    float4 v = src[i];
    __half h0 = __float2half_rn(v.x), h1 = __float2half_rn(v.y);
    __half h2 = __float2half_rn(v.z), h3 = __float2half_rn(v.w);
    uint2 hv, lv;
    hv.x = pk2h(v.x, v.y);                         // same as packing h0,h1
    hv.y = pk2h(v.z, v.w);
    lv.x = pk2h(v.x - __half2float(h0), v.y - __half2float(h1));
    lv.y = pk2h(v.z - __half2float(h2), v.w - __half2float(h3));
    hi[i] = hv;
    lo[i] = lv;
}

__global__ __launch_bounds__(256) void split1_h(const float4* __restrict__ src,
                                                uint2* __restrict__ dst, int n4)
{
    int i = blockIdx.x * blockDim.x + threadIdx.x;
    if (i >= n4) return;
    float4 v = src[i];
    uint2 o;
    o.x = pk2h(v.x, v.y);
    o.y = pk2h(v.z, v.w);
    dst[i] = o;
}

// ======================= HMMA GEMM (fp16x2, cp.async 3-stage, 2 CTA/SM) =====
// C[M,N] = (Ahi+Alo)[M,768] @ B[N,768]^T, A hi/lo fp16, B single fp16.
// stage: Ahi 8KB @0, Alo 8KB @8192, B 8KB @16384 -> 24576 B
#define GEMM_STAGE 24576
#define GEMM_SMEM  (3 * GEMM_STAGE)

template<bool QKV>
__global__ __launch_bounds__(256, 2) void mma_gemm(float* __restrict__ C,
                                                   const __half* __restrict__ Bh)
{
    extern __shared__ char sm[];
    const int tid  = threadIdx.x;
    const int lane = tid & 31;
    const int wid  = tid >> 5;
    const int wm   = wid & 3;
    const int wn   = wid >> 2;
    const int row0 = blockIdx.y * 128;
    const int col0 = blockIdx.x * 128;
    const uint32_t smem = smem_to_u32(sm);

    const int lr = tid >> 2;
    const int lc = tid & 3;

    const int arow[2] = { wm * 32 + 0 * 16 + (lane & 7) + ((lane >> 3) & 1) * 8,
                          wm * 32 + 1 * 16 + (lane & 7) + ((lane >> 3) & 1) * 8 };
    const int achk = lane >> 4;
    const int brow[4] = { wn * 64 + 0 * 16 + (lane & 7) + (lane >> 4) * 8,
                          wn * 64 + 1 * 16 + (lane & 7) + (lane >> 4) * 8,
                          wn * 64 + 2 * 16 + (lane & 7) + (lane >> 4) * 8,
                          wn * 64 + 3 * 16 + (lane & 7) + (lane >> 4) * 8 };
    const int bchk = (lane >> 3) & 1;

#define ISSUE(s_)                                                              \
    {                                                                          \
        uint32_t sb_ = smem + ((s_) % 3) * GEMM_STAGE;                         \
        int k0_ = (s_) * 32;                                                   \
        _Pragma("unroll")                                                      \
        for (int p = 0; p < 2; p++) {                                          \
            int r = lr + p * 64;                                               \
            int rA = row0 + r;                                                 \
            uint32_t szA = (rA < M_ROWS) ? 16u : 0u;                           \
            size_t offA = (size_t)(rA < M_ROWS ? rA : 0) * E_DIM + k0_ + lc * 8; \
            size_t offB = (size_t)(col0 + r) * E_DIM + k0_ + lc * 8;           \
            uint32_t co = CHUNK_OFF(r, lc);                                    \
            asm volatile("cp.async.cg.shared.global [%0], [%1], 16, %2;"       \
                :: "r"(sb_ + co), "l"(g_ahi + offA), "r"(szA));                \
            asm volatile("cp.async.cg.shared.global [%0], [%1], 16, %2;"       \
                :: "r"(sb_ + 8192 + co), "l"(g_alo + offA), "r"(szA));         \
            asm volatile("cp.async.cg.shared.global [%0], [%1], 16;"           \
                :: "r"(sb_ + 16384 + co), "l"(Bh + offB));                     \
        }                                                                      \
        asm volatile("cp.async.commit_group;");                                \
    }

    ISSUE(0)
    ISSUE(1)

    float acc[2][8][4] = {};

    for (int s = 0; s < 24; s++) {
        if (s + 1 < 24) asm volatile("cp.async.wait_group 1;");
        else            asm volatile("cp.async.wait_group 0;");
        __syncthreads();
        if (s + 2 < 24) ISSUE(s + 2)

        const uint32_t sb = smem + (s % 3) * GEMM_STAGE;
#pragma unroll
        for (int ks = 0; ks < 2; ks++) {
            uint32_t ah[2][4], al[2][4];
#pragma unroll
            for (int i = 0; i < 2; i++) {
                uint32_t adr = sb + CHUNK_OFF(arow[i], ks * 2 + achk);
                LDSM4(ah[i], adr);
                LDSM4(al[i], adr + 8192);
            }
            uint32_t bf[4][4];
#pragma unroll
            for (int g = 0; g < 4; g++) {
                uint32_t adr = sb + 16384 + CHUNK_OFF(brow[g], ks * 2 + bchk);
                LDSM4(bf[g], adr);
            }
#pragma unroll
            for (int i = 0; i < 2; i++)
#pragma unroll
                for (int g = 0; g < 4; g++)
#pragma unroll
                    for (int hh = 0; hh < 2; hh++) {
                        const int j = g * 2 + hh;
                        MMA16816(acc[i][j], ah[i], bf[g][hh*2], bf[g][hh*2+1]);
                        MMA16816(acc[i][j], al[i], bf[g][hh*2], bf[g][hh*2+1]);
                    }
        }
    }
#undef ISSUE

#pragma unroll
    for (int i = 0; i < 2; i++)
#pragma unroll
        for (int half = 0; half < 2; half++) {
            int m = row0 + wm * 32 + i * 16 + (lane >> 2) + half * 8;
            if (m >= M_ROWS) continue;
            int bb = 0, sIdx = 0;
            if (QKV) { bb = m / S_LEN; sIdx = m - bb * S_LEN; }
#pragma unroll
            for (int j = 0; j < 8; j++) {
                int n = col0 + wn * 64 + j * 8 + (lane & 3) * 2;
                float2 v = make_float2(acc[i][j][half*2], acc[i][j][half*2+1]);
                if (QKV) {
                    int t = n / E_DIM, r = n - t * E_DIM;
                    int h = r >> 6, d = r & 63;
                    *(float2*)&g_qkv[(size_t)t * HSTRIDE
                        + (((size_t)bb * NH + h) * S_LEN + sIdx) * DH + d] = v;
                } else {
                    *(float2*)&C[(size_t)m * E_DIM + n] = v;
                }
            }
        }
}

// ======================= convert: rope (table) + fp16 prep ==================
__global__ __launch_bounds__(256) void convert_rope_split()
{
    const int bh    = blockIdx.y;
    const int chunk = blockIdx.x;
    const int s0    = chunk * 64;
    const int tid   = threadIdx.x;
    const int wid   = tid >> 5, lane = tid & 31;
    const unsigned full = 0xffffffffu;

    __shared__ float ct[24][16], st[24][16];
    for (int e = tid; e < 384; e += 256) {
        int v = e >> 4, f = e & 15;
        float dv = expf(-(float)(2 * f) * (9.210340371976184f / 32.0f));
        float a  = (float)v * (1.0f / 23.00000001f) * dv;
        ct[v][f] = cosf(a);
        st[v][f] = sinf(a);
    }
    __syncthreads();

    const int fi = lane >> 1;

#pragma unroll
    for (int t = 0; t < 2; t++) {
#pragma unroll
        for (int ps = 0; ps < 8; ps++) {
            int s = s0 + ps * 8 + wid;
            float v0 = 0.f, v1 = 0.f;
            bool valid = (s < S_LEN);
            if (valid) {
                const float* base = g_qkv + (size_t)t * HSTRIDE
                                  + ((size_t)bh * S_LEN + s) * DH;
                v0 = base[lane];
                v1 = base[lane + 32];
            }
            float p0 = __shfl_sync(full, v0, (lane + 31) & 31);
            float p1 = __shfl_sync(full, v1, (lane + 31) & 31);
            if (valid && s > 0) {
                int p  = s - 1;
                int px = p % 24, py = p / 24;
                v0 = v0 * ct[px][fi] + p0 * st[px][fi];
                v1 = v1 * ct[py][fi] + p1 * st[py][fi];
            }
            if (valid) {
                size_t off = ((size_t)bh * S_LEN + s) * DH;
                if (t == 0) {
                    __half h0 = __float2half_rn(v0);
                    __half h1 = __float2half_rn(v1);
                    g_qhi[off + lane]      = h0;
                    g_qhi[off + lane + 32] = h1;
                    g_qlo[off + lane]      = __float2half_rn(v0 - __half2float(h0));
                    g_qlo[off + lane + 32] = __float2half_rn(v1 - __half2float(h1));
                } else {
                    g_kh[off + lane]      = __float2half_rn(v0);
                    g_kh[off + lane + 32] = __float2half_rn(v1);
                }
            }
        }
    }

    // V transpose -> g_vt fp16 [bh][d][s0..s0+64) (zeros beyond S_LEN)
    __shared__ float vbuf[64][65];
#pragma unroll
    for (int it = 0; it < 16; it++) {
        int idx = tid + it * 256;
        int r = idx >> 6, c = idx & 63;
        float val = (s0 + r < S_LEN)
            ? g_qkv[2 * HSTRIDE + ((size_t)bh * S_LEN + s0 + r) * DH + c] : 0.f;
        vbuf[c][r] = val;
    }
    __syncthreads();
    {
        int d = tid >> 2, grp = tid & 3;
        __half hh[16];
#pragma unroll
        for (int i = 0; i < 16; i++)
            hh[i] = __float2half_rn(vbuf[d][grp * 16 + i]);
        size_t dst = (size_t)bh * (DH * SPAD) + (size_t)d * SPAD + s0 + grp * 16;
        *(uint4*)(g_vt + dst)     = *(uint4*)hh;
        *(uint4*)(g_vt + dst + 8) = *(uint4*)(hh + 8);
    }
}

// ======================= HMMA flash attention (fp16x2, 48KB, 2 CTA/SM) ======
// Region A [0,32K): Q hi/lo staging; odd KV tiles reuse [0,16K).
// Region B [32K,48K): even KV tiles. KV tile: K 8KB + V 8KB.
#define FLASH_SMEM 49152

__global__ __launch_bounds__(256, 2) void flash_mma()
{
    extern __shared__ char sm[];
    const uint32_t smem = smem_to_u32(sm);

    const int bh  = blockIdx.y;
    const int i0  = blockIdx.x * 128;
    const int tid = threadIdx.x;
    const int lane = tid & 31, wid = tid >> 5;

#define KVBASE(t_) (smem + (((t_) & 1) ? 0u : 32768u))

#define ISSUE_KV(t_)                                                           \
    {                                                                          \
        uint32_t kb_ = KVBASE(t_);                                             \
        int j0_ = (t_) * 64;                                                   \
        _Pragma("unroll")                                                      \
        for (int it = 0; it < 2; it++) {                                       \
            int idx = tid + it * 256;                                          \
            int r = idx >> 3, c = idx & 7;                                     \
            int sj = j0_ + r;                                                  \
            uint32_t szK = (sj < S_LEN) ? 16u : 0u;                            \
            size_t koff = ((size_t)bh * S_LEN + (sj < S_LEN ? sj : 0)) * DH + c * 8; \
            size_t voff = (size_t)bh * (DH * SPAD) + (size_t)r * SPAD + j0_ + c * 8; \
            uint32_t co = CH8(r, c);                                           \
            asm volatile("cp.async.cg.shared.global [%0], [%1], 16, %2;"       \
                :: "r"(kb_ + co), "l"(g_kh + koff), "r"(szK));                 \
            asm volatile("cp.async.cg.shared.global [%0], [%1], 16;"           \
                :: "r"(kb_ + 8192 + co), "l"(g_vt + voff));                    \
        }                                                                      \
        asm volatile("cp.async.commit_group;");                                \
    }

    ISSUE_KV(0)

    // Q hi/lo staging into region A
#pragma unroll
    for (int it = 0; it < 4; it++) {
        int idx = tid + it * 256;
        int r = idx >> 3, c = idx & 7;
        int s = i0 + r;
        uint4 vh = make_uint4(0u,0u,0u,0u), vl = vh;
        if (s < S_LEN) {
            size_t off = ((size_t)bh * S_LEN + s) * DH + c * 8;
            vh = *(const uint4*)(g_qhi + off);
            vl = *(const uint4*)(g_qlo + off);
        }
        *(uint4*)(sm + CH8(r, c)) = vh;
        *(uint4*)(sm + 16384 + CH8(r, c)) = vl;
    }
    __syncthreads();

    uint32_t qhf[4][4], qlf[4][4];
    {
        const int ar = wid * 16 + (lane & 7) + ((lane >> 3) & 1) * 8;
        const int ac = lane >> 4;
#pragma unroll
        for (int kt = 0; kt < 4; kt++) {
            LDSM4(qhf[kt], smem + CH8(ar, kt * 2 + ac));
            LDSM4(qlf[kt], smem + 16384 + CH8(ar, kt * 2 + ac));
        }
    }
    __syncthreads();   // Q reads done before KV(1) overwrites region A

    ISSUE_KV(1)

    float oacc[8][4] = {};
    float m0 = -1e30f, m1 = -1e30f, l0 = 0.f, l1 = 0.f;

    const int br = (lane & 7) + ((lane >> 4) << 3);
    const int bc = (lane >> 3) & 1;

    for (int t = 0; t < 10; t++) {
        const int j0 = t * 64;
        if (t < 8) asm volatile("cp.async.wait_group 1;");
        else       asm volatile("cp.async.wait_group 0;");
        __syncthreads();

        const uint32_t kvb  = KVBASE(t);
        const uint32_t kh32 = kvb, vh32 = kvb + 8192;

        float sacc[8][4] = {};
#pragma unroll
        for (int kt = 0; kt < 4; kt++) {
            uint32_t khf[4][4];
#pragma unroll
            for (int g = 0; g < 4; g++)
                LDSM4(khf[g], kh32 + CH8(g * 16 + br, kt * 2 + bc));
#pragma unroll
            for (int g = 0; g < 4; g++)
#pragma unroll
                for (int hh = 0; hh < 2; hh++) {
                    const int j = g * 2 + hh;
                    MMA16816(sacc[j], qhf[kt], khf[g][hh*2], khf[g][hh*2+1]);
                    MMA16816(sacc[j], qlf[kt], khf[g][hh*2], khf[g][hh*2+1]);
                }
        }

        float tm0 = -1e30f, tm1 = -1e30f;
#pragma unroll
        for (int nt = 0; nt < 8; nt++) {
            int jb = j0 + nt * 8 + (lane & 3) * 2;
            sacc[nt][0] = (jb     < S_LEN) ? sacc[nt][0] * 0.125f : -1e30f;
            sacc[nt][1] = (jb + 1 < S_LEN) ? sacc[nt][1] * 0.125f : -1e30f;
            sacc[nt][2] = (jb     < S_LEN) ? sacc[nt][2] * 0.125f : -1e30f;
            sacc[nt][3] = (jb + 1 < S_LEN) ? sacc[nt][3] * 0.125f : -1e30f;
            tm0 = fmaxf(tm0, fmaxf(sacc[nt][0], sacc[nt][1]));
            tm1 = fmaxf(tm1, fmaxf(sacc[nt][2], sacc[nt][3]));
        }
        tm0 = fmaxf(tm0, __shfl_xor_sync(0xffffffffu, tm0, 1));
        tm0 = fmaxf(tm0, __shfl_xor_sync(0xffffffffu, tm0, 2));
        tm1 = fmaxf(tm1, __shfl_xor_sync(0xffffffffu, tm1, 1));
        tm1 = fmaxf(tm1, __shfl_xor_sync(0xffffffffu, tm1, 2));
        float mn0 = fmaxf(m0, tm0), mn1 = fmaxf(m1, tm1);
        float f0 = __expf(m0 - mn0), f1 = __expf(m1 - mn1);
        m0 = mn0; m1 = mn1;

        float rs0 = 0.f, rs1 = 0.f;
#pragma unroll
        for (int nt = 0; nt < 8; nt++) {
            sacc[nt][0] = __expf(sacc[nt][0] - mn0);
            sacc[nt][1] = __expf(sacc[nt][1] - mn0);
            sacc[nt][2] = __expf(sacc[nt][2] - mn1);
            sacc[nt][3] = __expf(sacc[nt][3] - mn1);
            rs0 += sacc[nt][0] + sacc[nt][1];
            rs1 += sacc[nt][2] + sacc[nt][3];
        }
        rs0 += __shfl_xor_sync(0xffffffffu, rs0, 1);
        rs0 += __shfl_xor_sync(0xffffffffu, rs0, 2);
        rs1 += __shfl_xor_sync(0xffffffffu, rs1, 1);
        rs1 += __shfl_xor_sync(0xffffffffu, rs1, 2);
        l0 = l0 * f0 + rs0;
        l1 = l1 * f1 + rs1;

#pragma unroll
        for (int nt = 0; nt < 8; nt++) {
            oacc[nt][0] *= f0; oacc[nt][1] *= f0;
            oacc[nt][2] *= f1; oacc[nt][3] *= f1;
        }

        // P -> fp16 hi + residual lo, packed as A-fragments
        uint32_t pahi[4][4], palo[4][4];
#pragma unroll
        for (int kt = 0; kt < 4; kt++) {
            const int t0 = kt * 2, t1 = kt * 2 + 1;
            float v00 = sacc[t0][0], v01 = sacc[t0][1];
            float v02 = sacc[t0][2], v03 = sacc[t0][3];
            float v10 = sacc[t1][0], v11 = sacc[t1][1];
            float v12 = sacc[t1][2], v13 = sacc[t1][3];
            pahi[kt][0] = pk2h(v00, v01);
            pahi[kt][1] = pk2h(v02, v03);
            pahi[kt][2] = pk2h(v10, v11);
            pahi[kt][3] = pk2h(v12, v13);
            palo[kt][0] = pk2h(v00 - __half2float(__float2half_rn(v00)),
                               v01 - __half2float(__float2half_rn(v01)));
            palo[kt][1] = pk2h(v02 - __half2float(__float2half_rn(v02)),
                               v03 - __half2float(__float2half_rn(v03)));
            palo[kt][2] = pk2h(v10 - __half2float(__float2half_rn(v10)),
                               v11 - __half2float(__float2half_rn(v11)));
            palo[kt][3] = pk2h(v12 - __half2float(__float2half_rn(v12)),
                               v13 - __half2float(__float2half_rn(v13)));
        }

#pragma unroll
        for (int kt = 0; kt < 4; kt++) {
            uint32_t vhf[4][4];
#pragma unroll
            for (int g = 0; g < 4; g++)
                LDSM4(vhf[g], vh32 + CH8(g * 16 + br, kt * 2 + bc));
#pragma unroll
            for (int g = 0; g < 4; g++)
#pragma unroll
                for (int hh = 0; hh < 2; hh++) {
                    const int j = g * 2 + hh;
                    MMA16816(oacc[j], pahi[kt], vhf[g][hh*2], vhf[g][hh*2+1]);
                    MMA16816(oacc[j], palo[kt], vhf[g][hh*2], vhf[g][hh*2+1]);
                }
        }
        __syncthreads();
        if (t + 2 < 10) ISSUE_KV(t + 2)
    }
#undef ISSUE_KV
#undef KVBASE

    // epilogue: ctx as fp16 hi/lo into g_ahi/g_alo (A of out-proj GEMM)
    const float inv0 = 1.f / l0, inv1 = 1.f / l1;
    const int b = bh / NH, h = bh % NH;
    const int r0 = i0 + wid * 16 + (lane >> 2);
    const int r1 = r0 + 8;
#pragma unroll
    for (int nt = 0; nt < 8; nt++) {
        int d = nt * 8 + (lane & 3) * 2;
        if (r0 < S_LEN) {
            float o0 = oacc[nt][0] * inv0, o1 = oacc[nt][1] * inv0;
            size_t off = ((size_t)b * S_LEN + r0) * E_DIM + h * DH + d;
            *(uint32_t*)&g_ahi[off] = pk2h(o0, o1);
            *(uint32_t*)&g_alo[off] = pk2h(o0 - __half2float(__float2half_rn(o0)),
                                           o1 - __half2float(__float2half_rn(o1)));
        }
        if (r1 < S_LEN) {
            float o2 = oacc[nt][2] * inv1, o3 = oacc[nt][3] * inv1;
            size_t off = ((size_t)b * S_LEN + r1) * E_DIM + h * DH + d;
            *(uint32_t*)&g_ahi[off] = pk2h(o2, o3);
            *(uint32_t*)&g_alo[off] = pk2h(o2 - __half2float(__float2half_rn(o2)),
                                           o3 - __half2float(__float2half_rn(o3)));
        }
    }
}

// ======================= launch =============================================
extern "C" void kernel_launch(void* const* d_in, const int* in_sizes, int n_in,
                              void* d_out, int out_size)
{
    (void)in_sizes; (void)n_in; (void)out_size;
    const float* x      = (const float*)d_in[0];
    const float* w_qkv  = (const float*)d_in[1];
    const float* w_proj = (const float*)d_in[2];
    float* out = (float*)d_out;

    void *ahi, *alo, *bh, *ph;
    cudaGetSymbolAddress(&ahi, g_ahi);
    cudaGetSymbolAddress(&alo, g_alo);
    cudaGetSymbolAddress(&bh, g_bh);
    cudaGetSymbolAddress(&ph, g_ph);

    cudaFuncSetAttribute(mma_gemm<true>,  cudaFuncAttributeMaxDynamicSharedMemorySize, GEMM_SMEM);
    cudaFuncSetAttribute(mma_gemm<false>, cudaFuncAttributeMaxDynamicSharedMemorySize, GEMM_SMEM);
    cudaFuncSetAttribute(flash_mma, cudaFuncAttributeMaxDynamicSharedMemorySize, FLASH_SMEM);

    const int MT = (M_ROWS + 127) / 128;   // 145

    // 1) input conversions up front
    {
        int n4 = M_ROWS * E_DIM / 4;
        split2_h<<<(n4 + 255) / 256, 256>>>((const float4*)x, (uint2*)ahi, (uint2*)alo, n4);
        int w4 = QKV_F * E_DIM / 4;
        split1_h<<<(w4 + 255) / 256, 256>>>((const float4*)w_qkv, (uint2*)bh, w4);
        int p4 = E_DIM * E_DIM / 4;
        split1_h<<<(p4 + 255) / 256, 256>>>((const float4*)w_proj, (uint2*)ph, p4);
    }

    // 2) QKV projection -> g_qkv fp32 [t][b][h][s][d]
    mma_gemm<true><<<dim3(QKV_F / 128, MT), 256, GEMM_SMEM>>>(
        nullptr, (const __half*)bh);

    // 3) rope (table) + fp16 prep of q (hi/lo), k (single), V^T (single)
    convert_rope_split<<<dim3(10, BH), 256>>>();

    // 4) HMMA flash attention -> ctx as fp16 hi/lo into g_ahi/g_alo
    flash_mma<<<dim3(5, BH), 256, FLASH_SMEM>>>();

    // 5) output projection
    mma_gemm<false><<<dim3(E_DIM / 128, MT), 256, GEMM_SMEM>>>(
        out, (const __half*)ph);
}

// round 14
// speedup vs baseline: 1.3699x; 1.0076x over previous
#include <cuda_runtime.h>
#include <cuda_fp16.h>
#include <math.h>
#include <stdint.h>

#define B_SZ   32
#define S_LEN  577
#define E_DIM  768
#define NH     12
#define DH     64
#define BH     (B_SZ * NH)         // 384
#define M_ROWS (B_SZ * S_LEN)      // 18464
#define QKV_F  (3 * E_DIM)         // 2304
#define SPAD   640
#define HSTRIDE ((size_t)B_SZ * NH * S_LEN * DH)

// Scratch (device globals; allocation-free per harness rules)
__device__ float g_qkv[(size_t)3 * B_SZ * NH * S_LEN * DH];  // [t][b][h][s][d]
__device__ __half g_ahi[(size_t)M_ROWS * E_DIM];   // A hi (x, then ctx)
__device__ __half g_alo[(size_t)M_ROWS * E_DIM];   // A lo
__device__ __half g_bh [(size_t)QKV_F * E_DIM];    // w_qkv fp16
__device__ __half g_ph [(size_t)E_DIM * E_DIM];    // w_proj fp16
// flash operands
__device__ __half g_qhi[(size_t)BH * S_LEN * DH];
__device__ __half g_qlo[(size_t)BH * S_LEN * DH];
__device__ __half g_kh [(size_t)BH * S_LEN * DH];
__device__ __half g_vt [(size_t)BH * DH * SPAD];   // V^T fp16 [bh][d][s]

__device__ __forceinline__ uint32_t smem_to_u32(const void* p) {
    uint32_t a;
    asm("{ .reg .u64 t; cvta.to.shared.u64 t, %1; cvt.u32.u64 %0, t; }" : "=r"(a) : "l"(p));
    return a;
}

// ---- mma.sync helpers (fp16 in, fp32 accum) ----
#define LDSM4(r, addr)                                                         \
    asm volatile("ldmatrix.sync.aligned.m8n8.x4.shared.b16 {%0,%1,%2,%3}, [%4];" \
        : "=r"((r)[0]), "=r"((r)[1]), "=r"((r)[2]), "=r"((r)[3]) : "r"(addr))

#define MMA16816(d, a, b0, b1)                                                 \
    asm volatile("mma.sync.aligned.m16n8k16.row.col.f32.f16.f16.f32 "          \
        "{%0,%1,%2,%3}, {%4,%5,%6,%7}, {%8,%9}, {%0,%1,%2,%3};"                \
        : "+f"((d)[0]), "+f"((d)[1]), "+f"((d)[2]), "+f"((d)[3])               \
        : "r"((a)[0]), "r"((a)[1]), "r"((a)[2]), "r"((a)[3]), "r"(b0), "r"(b1))

// 16B-chunk swizzles
#define CHUNK_OFF(row, c) (((row) << 6) + ((((c) ^ (((row) >> 1) & 3))) << 4)) // [r][32 h16]
#define CH8(row, c)       (((row) << 7) + ((((c) ^ ((row) & 7))) << 4))        // [r][64 h16]

__device__ __forceinline__ uint32_t pk2h(float f0, float f1) {
    __half2 h = __floats2half2_rn(f0, f1);
    return *(uint32_t*)&h;
}

// ======================= fp16 splits ========================================
__global__ __launch_bounds__(256) void split2_h(const float4* __restrict__ src,
                                                uint2* __restrict__ hi,
                                                uint2* __restrict__ lo, int n4)
{
    int i = blockIdx.x * blockDim.x + threadIdx.x;
    if (i >= n4) return;
    float4 v = src[i];
    __half h0 = __float2half_rn(v.x), h1 = __float2half_rn(v.y);
    __half h2 = __float2half_rn(v.z), h3 = __float2half_rn(v.w);
    uint2 hv, lv;
    hv.x = pk2h(v.x, v.y);
    hv.y = pk2h(v.z, v.w);
    lv.x = pk2h(v.x - __half2float(h0), v.y - __half2float(h1));
    lv.y = pk2h(v.z - __half2float(h2), v.w - __half2float(h3));
    hi[i] = hv;
    lo[i] = lv;
}

__global__ __launch_bounds__(256) void split1_h(const float4* __restrict__ src,
                                                uint2* __restrict__ dst, int n4)
{
    int i = blockIdx.x * blockDim.x + threadIdx.x;
    if (i >= n4) return;
    float4 v = src[i];
    uint2 o;
    o.x = pk2h(v.x, v.y);
    o.y = pk2h(v.z, v.w);
    dst[i] = o;
}

// ======================= HMMA GEMM (fp16x2, cp.async 3-stage, 2 CTA/SM) =====
#define GEMM_STAGE 24576
#define GEMM_SMEM  (3 * GEMM_STAGE)

template<bool QKV>
__global__ __launch_bounds__(256, 2) void mma_gemm(float* __restrict__ C,
                                                   const __half* __restrict__ Bh)
{
    extern __shared__ char sm[];
    const int tid  = threadIdx.x;
    const int lane = tid & 31;
    const int wid  = tid >> 5;
    const int wm   = wid & 3;
    const int wn   = wid >> 2;
    const int row0 = blockIdx.y * 128;
    const int col0 = blockIdx.x * 128;
    const uint32_t smem = smem_to_u32(sm);

    const int lr = tid >> 2;
    const int lc = tid & 3;

    const int arow[2] = { wm * 32 + 0 * 16 + (lane & 7) + ((lane >> 3) & 1) * 8,
                          wm * 32 + 1 * 16 + (lane & 7) + ((lane >> 3) & 1) * 8 };
    const int achk = lane >> 4;
    const int brow[4] = { wn * 64 + 0 * 16 + (lane & 7) + (lane >> 4) * 8,
                          wn * 64 + 1 * 16 + (lane & 7) + (lane >> 4) * 8,
                          wn * 64 + 2 * 16 + (lane & 7) + (lane >> 4) * 8,
                          wn * 64 + 3 * 16 + (lane & 7) + (lane >> 4) * 8 };
    const int bchk = (lane >> 3) & 1;

#define ISSUE(s_)                                                              \
    {                                                                          \
        uint32_t sb_ = smem + ((s_) % 3) * GEMM_STAGE;                         \
        int k0_ = (s_) * 32;                                                   \
        _Pragma("unroll")                                                      \
        for (int p = 0; p < 2; p++) {                                          \
            int r = lr + p * 64;                                               \
            int rA = row0 + r;                                                 \
            uint32_t szA = (rA < M_ROWS) ? 16u : 0u;                           \
            size_t offA = (size_t)(rA < M_ROWS ? rA : 0) * E_DIM + k0_ + lc * 8; \
            size_t offB = (size_t)(col0 + r) * E_DIM + k0_ + lc * 8;           \
            uint32_t co = CHUNK_OFF(r, lc);                                    \
            asm volatile("cp.async.cg.shared.global [%0], [%1], 16, %2;"       \
                :: "r"(sb_ + co), "l"(g_ahi + offA), "r"(szA));                \
            asm volatile("cp.async.cg.shared.global [%0], [%1], 16, %2;"       \
                :: "r"(sb_ + 8192 + co), "l"(g_alo + offA), "r"(szA));         \
            asm volatile("cp.async.cg.shared.global [%0], [%1], 16;"           \
                :: "r"(sb_ + 16384 + co), "l"(Bh + offB));                     \
        }                                                                      \
        asm volatile("cp.async.commit_group;");                                \
    }

    ISSUE(0)
    ISSUE(1)

    float acc[2][8][4] = {};

    for (int s = 0; s < 24; s++) {
        if (s + 1 < 24) asm volatile("cp.async.wait_group 1;");
        else            asm volatile("cp.async.wait_group 0;");
        __syncthreads();
        if (s + 2 < 24) ISSUE(s + 2)

        const uint32_t sb = smem + (s % 3) * GEMM_STAGE;
#pragma unroll
        for (int ks = 0; ks < 2; ks++) {
            uint32_t ah[2][4], al[2][4];
#pragma unroll
            for (int i = 0; i < 2; i++) {
                uint32_t adr = sb + CHUNK_OFF(arow[i], ks * 2 + achk);
                LDSM4(ah[i], adr);
                LDSM4(al[i], adr + 8192);
            }
            uint32_t bf[4][4];
#pragma unroll
            for (int g = 0; g < 4; g++) {
                uint32_t adr = sb + 16384 + CHUNK_OFF(brow[g], ks * 2 + bchk);
                LDSM4(bf[g], adr);
            }
            // pass 1: all hi-MMAs (16 independent accumulators)
#pragma unroll
            for (int i = 0; i < 2; i++)
#pragma unroll
                for (int g = 0; g < 4; g++)
#pragma unroll
                    for (int hh = 0; hh < 2; hh++)
                        MMA16816(acc[i][g*2+hh], ah[i], bf[g][hh*2], bf[g][hh*2+1]);
            // pass 2: all lo-MMAs (RAW distance = 16 MMAs)
#pragma unroll
            for (int i = 0; i < 2; i++)
#pragma unroll
                for (int g = 0; g < 4; g++)
#pragma unroll
                    for (int hh = 0; hh < 2; hh++)
                        MMA16816(acc[i][g*2+hh], al[i], bf[g][hh*2], bf[g][hh*2+1]);
        }
    }
#undef ISSUE

#pragma unroll
    for (int i = 0; i < 2; i++)
#pragma unroll
        for (int half = 0; half < 2; half++) {
            int m = row0 + wm * 32 + i * 16 + (lane >> 2) + half * 8;
            if (m >= M_ROWS) continue;
            int bb = 0, sIdx = 0;
            if (QKV) { bb = m / S_LEN; sIdx = m - bb * S_LEN; }
#pragma unroll
            for (int j = 0; j < 8; j++) {
                int n = col0 + wn * 64 + j * 8 + (lane & 3) * 2;
                float2 v = make_float2(acc[i][j][half*2], acc[i][j][half*2+1]);
                if (QKV) {
                    int t = n / E_DIM, r = n - t * E_DIM;
                    int h = r >> 6, d = r & 63;
                    *(float2*)&g_qkv[(size_t)t * HSTRIDE
                        + (((size_t)bb * NH + h) * S_LEN + sIdx) * DH + d] = v;
                } else {
                    *(float2*)&C[(size_t)m * E_DIM + n] = v;
                }
            }
        }
}

// ======================= convert: rope (table) + fp16 prep ==================
__global__ __launch_bounds__(256) void convert_rope_split()
{
    const int bh    = blockIdx.y;
    const int chunk = blockIdx.x;
    const int s0    = chunk * 64;
    const int tid   = threadIdx.x;
    const int wid   = tid >> 5, lane = tid & 31;
    const unsigned full = 0xffffffffu;

    __shared__ float ct[24][16], st[24][16];
    for (int e = tid; e < 384; e += 256) {
        int v = e >> 4, f = e & 15;
        float dv = expf(-(float)(2 * f) * (9.210340371976184f / 32.0f));
        float a  = (float)v * (1.0f / 23.00000001f) * dv;
        ct[v][f] = cosf(a);
        st[v][f] = sinf(a);
    }
    __syncthreads();

    const int fi = lane >> 1;

#pragma unroll
    for (int t = 0; t < 2; t++) {
#pragma unroll
        for (int ps = 0; ps < 8; ps++) {
            int s = s0 + ps * 8 + wid;
            float v0 = 0.f, v1 = 0.f;
            bool valid = (s < S_LEN);
            if (valid) {
                const float* base = g_qkv + (size_t)t * HSTRIDE
                                  + ((size_t)bh * S_LEN + s) * DH;
                v0 = base[lane];
                v1 = base[lane + 32];
            }
            float p0 = __shfl_sync(full, v0, (lane + 31) & 31);
            float p1 = __shfl_sync(full, v1, (lane + 31) & 31);
            if (valid && s > 0) {
                int p  = s - 1;
                int px = p % 24, py = p / 24;
                v0 = v0 * ct[px][fi] + p0 * st[px][fi];
                v1 = v1 * ct[py][fi] + p1 * st[py][fi];
            }
            if (valid) {
                size_t off = ((size_t)bh * S_LEN + s) * DH;
                if (t == 0) {
                    __half h0 = __float2half_rn(v0);
                    __half h1 = __float2half_rn(v1);
                    g_qhi[off + lane]      = h0;
                    g_qhi[off + lane + 32] = h1;
                    g_qlo[off + lane]      = __float2half_rn(v0 - __half2float(h0));
                    g_qlo[off + lane + 32] = __float2half_rn(v1 - __half2float(h1));
                } else {
                    g_kh[off + lane]      = __float2half_rn(v0);
                    g_kh[off + lane + 32] = __float2half_rn(v1);
                }
            }
        }
    }

    // V transpose -> g_vt fp16 [bh][d][s0..s0+64) (zeros beyond S_LEN)
    __shared__ float vbuf[64][65];
#pragma unroll
    for (int it = 0; it < 16; it++) {
        int idx = tid + it * 256;
        int r = idx >> 6, c = idx & 63;
        float val = (s0 + r < S_LEN)
            ? g_qkv[2 * HSTRIDE + ((size_t)bh * S_LEN + s0 + r) * DH + c] : 0.f;
        vbuf[c][r] = val;
    }
    __syncthreads();
    {
        int d = tid >> 2, grp = tid & 3;
        __half hh[16];
#pragma unroll
        for (int i = 0; i < 16; i++)
            hh[i] = __float2half_rn(vbuf[d][grp * 16 + i]);
        size_t dst = (size_t)bh * (DH * SPAD) + (size_t)d * SPAD + s0 + grp * 16;
        *(uint4*)(g_vt + dst)     = *(uint4*)hh;
        *(uint4*)(g_vt + dst + 8) = *(uint4*)(hh + 8);
    }
}

// ======================= HMMA flash attention (fp16x2, 48KB, 2 CTA/SM) ======
#define FLASH_SMEM 49152

__global__ __launch_bounds__(256, 2) void flash_mma()
{
    extern __shared__ char sm[];
    const uint32_t smem = smem_to_u32(sm);

    const int bh  = blockIdx.y;
    const int i0  = blockIdx.x * 128;
    const int tid = threadIdx.x;
    const int lane = tid & 31, wid = tid >> 5;

#define KVBASE(t_) (smem + (((t_) & 1) ? 0u : 32768u))

#define ISSUE_KV(t_)                                                           \
    {                                                                          \
        uint32_t kb_ = KVBASE(t_);                                             \
        int j0_ = (t_) * 64;                                                   \
        _Pragma("unroll")                                                      \
        for (int it = 0; it < 2; it++) {                                       \
            int idx = tid + it * 256;                                          \
            int r = idx >> 3, c = idx & 7;                                     \
            int sj = j0_ + r;                                                  \
            uint32_t szK = (sj < S_LEN) ? 16u : 0u;                            \
            size_t koff = ((size_t)bh * S_LEN + (sj < S_LEN ? sj : 0)) * DH + c * 8; \
            size_t voff = (size_t)bh * (DH * SPAD) + (size_t)r * SPAD + j0_ + c * 8; \
            uint32_t co = CH8(r, c);                                           \
            asm volatile("cp.async.cg.shared.global [%0], [%1], 16, %2;"       \
                :: "r"(kb_ + co), "l"(g_kh + koff), "r"(szK));                 \
            asm volatile("cp.async.cg.shared.global [%0], [%1], 16;"           \
                :: "r"(kb_ + 8192 + co), "l"(g_vt + voff));                    \
        }                                                                      \
        asm volatile("cp.async.commit_group;");                                \
    }

    ISSUE_KV(0)

#pragma unroll
    for (int it = 0; it < 4; it++) {
        int idx = tid + it * 256;
        int r = idx >> 3, c = idx & 7;
        int s = i0 + r;
        uint4 vh = make_uint4(0u,0u,0u,0u), vl = vh;
        if (s < S_LEN) {
            size_t off = ((size_t)bh * S_LEN + s) * DH + c * 8;
            vh = *(const uint4*)(g_qhi + off);
            vl = *(const uint4*)(g_qlo + off);
        }
        *(uint4*)(sm + CH8(r, c)) = vh;
        *(uint4*)(sm + 16384 + CH8(r, c)) = vl;
    }
    __syncthreads();

    uint32_t qhf[4][4], qlf[4][4];
    {
        const int ar = wid * 16 + (lane & 7) + ((lane >> 3) & 1) * 8;
        const int ac = lane >> 4;
#pragma unroll
        for (int kt = 0; kt < 4; kt++) {
            LDSM4(qhf[kt], smem + CH8(ar, kt * 2 + ac));
            LDSM4(qlf[kt], smem + 16384 + CH8(ar, kt * 2 + ac));
        }
    }
    __syncthreads();

    ISSUE_KV(1)

    float oacc[8][4] = {};
    float m0 = -1e30f, m1 = -1e30f, l0 = 0.f, l1 = 0.f;

    const int br = (lane & 7) + ((lane >> 4) << 3);
    const int bc = (lane >> 3) & 1;

    for (int t = 0; t < 10; t++) {
        const int j0 = t * 64;
        if (t < 8) asm volatile("cp.async.wait_group 1;");
        else       asm volatile("cp.async.wait_group 0;");
        __syncthreads();

        const uint32_t kvb  = KVBASE(t);
        const uint32_t kh32 = kvb, vh32 = kvb + 8192;

        float sacc[8][4] = {};
#pragma unroll
        for (int kt = 0; kt < 4; kt++) {
            uint32_t khf[4][4];
#pragma unroll
            for (int g = 0; g < 4; g++)
                LDSM4(khf[g], kh32 + CH8(g * 16 + br, kt * 2 + bc));
            // pass 1: hi (8 independent accs), pass 2: lo (RAW distance 8)
#pragma unroll
            for (int g = 0; g < 4; g++)
#pragma unroll
                for (int hh = 0; hh < 2; hh++)
                    MMA16816(sacc[g*2+hh], qhf[kt], khf[g][hh*2], khf[g][hh*2+1]);
#pragma unroll
            for (int g = 0; g < 4; g++)
#pragma unroll
                for (int hh = 0; hh < 2; hh++)
                    MMA16816(sacc[g*2+hh], qlf[kt], khf[g][hh*2], khf[g][hh*2+1]);
        }

        float tm0 = -1e30f, tm1 = -1e30f;
#pragma unroll
        for (int nt = 0; nt < 8; nt++) {
            int jb = j0 + nt * 8 + (lane & 3) * 2;
            sacc[nt][0] = (jb     < S_LEN) ? sacc[nt][0] * 0.125f : -1e30f;
            sacc[nt][1] = (jb + 1 < S_LEN) ? sacc[nt][1] * 0.125f : -1e30f;
            sacc[nt][2] = (jb     < S_LEN) ? sacc[nt][2] * 0.125f : -1e30f;
            sacc[nt][3] = (jb + 1 < S_LEN) ? sacc[nt][3] * 0.125f : -1e30f;
            tm0 = fmaxf(tm0, fmaxf(sacc[nt][0], sacc[nt][1]));
            tm1 = fmaxf(tm1, fmaxf(sacc[nt][2], sacc[nt][3]));
        }
        tm0 = fmaxf(tm0, __shfl_xor_sync(0xffffffffu, tm0, 1));
        tm0 = fmaxf(tm0, __shfl_xor_sync(0xffffffffu, tm0, 2));
        tm1 = fmaxf(tm1, __shfl_xor_sync(0xffffffffu, tm1, 1));
        tm1 = fmaxf(tm1, __shfl_xor_sync(0xffffffffu, tm1, 2));
        float mn0 = fmaxf(m0, tm0), mn1 = fmaxf(m1, tm1);
        float f0 = __expf(m0 - mn0), f1 = __expf(m1 - mn1);
        m0 = mn0; m1 = mn1;

        float rs0 = 0.f, rs1 = 0.f;
#pragma unroll
        for (int nt = 0; nt < 8; nt++) {
            sacc[nt][0] = __expf(sacc[nt][0] - mn0);
            sacc[nt][1] = __expf(sacc[nt][1] - mn0);
            sacc[nt][2] = __expf(sacc[nt][2] - mn1);
            sacc[nt][3] = __expf(sacc[nt][3] - mn1);
            rs0 += sacc[nt][0] + sacc[nt][1];
            rs1 += sacc[nt][2] + sacc[nt][3];
        }
        rs0 += __shfl_xor_sync(0xffffffffu, rs0, 1);
        rs0 += __shfl_xor_sync(0xffffffffu, rs0, 2);
        rs1 += __shfl_xor_sync(0xffffffffu, rs1, 1);
        rs1 += __shfl_xor_sync(0xffffffffu, rs1, 2);
        l0 = l0 * f0 + rs0;
        l1 = l1 * f1 + rs1;

#pragma unroll
        for (int nt = 0; nt < 8; nt++) {
            oacc[nt][0] *= f0; oacc[nt][1] *= f0;
            oacc[nt][2] *= f1; oacc[nt][3] *= f1;
        }

        uint32_t pahi[4][4], palo[4][4];
#pragma unroll
        for (int kt = 0; kt < 4; kt++) {
            const int t0 = kt * 2, t1 = kt * 2 + 1;
            float v00 = sacc[t0][0], v01 = sacc[t0][1];
            float v02 = sacc[t0][2], v03 = sacc[t0][3];
            float v10 = sacc[t1][0], v11 = sacc[t1][1];
            float v12 = sacc[t1][2], v13 = sacc[t1][3];
            pahi[kt][0] = pk2h(v00, v01);
            pahi[kt][1] = pk2h(v02, v03);
            pahi[kt][2] = pk2h(v10, v11);
            pahi[kt][3] = pk2h(v12, v13);
            palo[kt][0] = pk2h(v00 - __half2float(__float2half_rn(v00)),
                               v01 - __half2float(__float2half_rn(v01)));
            palo[kt][1] = pk2h(v02 - __half2float(__float2half_rn(v02)),
                               v03 - __half2float(__float2half_rn(v03)));
            palo[kt][2] = pk2h(v10 - __half2float(__float2half_rn(v10)),
                               v11 - __half2float(__float2half_rn(v11)));
            palo[kt][3] = pk2h(v12 - __half2float(__float2half_rn(v12)),
                               v13 - __half2float(__float2half_rn(v13)));
        }

#pragma unroll
        for (int kt = 0; kt < 4; kt++) {
            uint32_t vhf[4][4];
#pragma unroll
            for (int g = 0; g < 4; g++)
                LDSM4(vhf[g], vh32 + CH8(g * 16 + br, kt * 2 + bc));
#pragma unroll
            for (int g = 0; g < 4; g++)
#pragma unroll
                for (int hh = 0; hh < 2; hh++)
                    MMA16816(oacc[g*2+hh], pahi[kt], vhf[g][hh*2], vhf[g][hh*2+1]);
#pragma unroll
            for (int g = 0; g < 4; g++)
#pragma unroll
                for (int hh = 0; hh < 2; hh++)
                    MMA16816(oacc[g*2+hh], palo[kt], vhf[g][hh*2], vhf[g][hh*2+1]);
        }
        __syncthreads();
        if (t + 2 < 10) ISSUE_KV(t + 2)
    }
#undef ISSUE_KV
#undef KVBASE

    // epilogue: ctx as fp16 hi/lo into g_ahi/g_alo (A of out-proj GEMM)
    const float inv0 = 1.f / l0, inv1 = 1.f / l1;
    const int b = bh / NH, h = bh % NH;
    const int r0 = i0 + wid * 16 + (lane >> 2);
    const int r1 = r0 + 8;
#pragma unroll
    for (int nt = 0; nt < 8; nt++) {
        int d = nt * 8 + (lane & 3) * 2;
        if (r0 < S_LEN) {
            float o0 = oacc[nt][0] * inv0, o1 = oacc[nt][1] * inv0;
            size_t off = ((size_t)b * S_LEN + r0) * E_DIM + h * DH + d;
            *(uint32_t*)&g_ahi[off] = pk2h(o0, o1);
            *(uint32_t*)&g_alo[off] = pk2h(o0 - __half2float(__float2half_rn(o0)),
                                           o1 - __half2float(__float2half_rn(o1)));
        }
        if (r1 < S_LEN) {
            float o2 = oacc[nt][2] * inv1, o3 = oacc[nt][3] * inv1;
            size_t off = ((size_t)b * S_LEN + r1) * E_DIM + h * DH + d;
            *(uint32_t*)&g_ahi[off] = pk2h(o2, o3);
            *(uint32_t*)&g_alo[off] = pk2h(o2 - __half2float(__float2half_rn(o2)),
                                           o3 - __half2float(__float2half_rn(o3)));
        }
    }
}

// ======================= launch =============================================
extern "C" void kernel_launch(void* const* d_in, const int* in_sizes, int n_in,
                              void* d_out, int out_size)
{
    (void)in_sizes; (void)n_in; (void)out_size;
    const float* x      = (const float*)d_in[0];
    const float* w_qkv  = (const float*)d_in[1];
    const float* w_proj = (const float*)d_in[2];
    float* out = (float*)d_out;

    void *ahi, *alo, *bh, *ph;
    cudaGetSymbolAddress(&ahi, g_ahi);
    cudaGetSymbolAddress(&alo, g_alo);
    cudaGetSymbolAddress(&bh, g_bh);
    cudaGetSymbolAddress(&ph, g_ph);

    cudaFuncSetAttribute(mma_gemm<true>,  cudaFuncAttributeMaxDynamicSharedMemorySize, GEMM_SMEM);
    cudaFuncSetAttribute(mma_gemm<false>, cudaFuncAttributeMaxDynamicSharedMemorySize, GEMM_SMEM);
    cudaFuncSetAttribute(flash_mma, cudaFuncAttributeMaxDynamicSharedMemorySize, FLASH_SMEM);

    const int MT = (M_ROWS + 127) / 128;   // 145

    // 1) input conversions up front
    {
        int n4 = M_ROWS * E_DIM / 4;
        split2_h<<<(n4 + 255) / 256, 256>>>((const float4*)x, (uint2*)ahi, (uint2*)alo, n4);
        int w4 = QKV_F * E_DIM / 4;
        split1_h<<<(w4 + 255) / 256, 256>>>((const float4*)w_qkv, (uint2*)bh, w4);
        int p4 = E_DIM * E_DIM / 4;
        split1_h<<<(p4 + 255) / 256, 256>>>((const float4*)w_proj, (uint2*)ph, p4);
    }

    // 2) QKV projection -> g_qkv fp32 [t][b][h][s][d]
    mma_gemm<true><<<dim3(QKV_F / 128, MT), 256, GEMM_SMEM>>>(
        nullptr, (const __half*)bh);

    // 3) rope (table) + fp16 prep of q (hi/lo), k (single), V^T (single)
    convert_rope_split<<<dim3(10, BH), 256>>>();

    // 4) HMMA flash attention -> ctx as fp16 hi/lo into g_ahi/g_alo
    flash_mma<<<dim3(5, BH), 256, FLASH_SMEM>>>();

    // 5) output projection
    mma_gemm<false><<<dim3(E_DIM / 128, MT), 256, GEMM_SMEM>>>(
        out, (const __half*)ph);
}

// round 15
// speedup vs baseline: 1.3923x; 1.0163x over previous
#include <cuda_runtime.h>
#include <cuda_fp16.h>
#include <math.h>
#include <stdint.h>

#define B_SZ   32
#define S_LEN  577
#define E_DIM  768
#define NH     12
#define DH     64
#define BH     (B_SZ * NH)         // 384
#define M_ROWS (B_SZ * S_LEN)      // 18464
#define QKV_F  (3 * E_DIM)         // 2304
#define SPAD   640
#define HSTRIDE ((size_t)BH * S_LEN * DH)

// Scratch (device globals; allocation-free per harness rules)
__device__ __half g_qpre[(size_t)BH * S_LEN * DH];  // pre-rope q fp16 [bh][s][d]
__device__ __half g_kpre[(size_t)BH * S_LEN * DH];  // pre-rope k fp16
__device__ __half g_vpre[(size_t)BH * S_LEN * DH];  // v fp16
__device__ __half g_ahi[(size_t)M_ROWS * E_DIM];    // A hi (x, then ctx)
__device__ __half g_alo[(size_t)M_ROWS * E_DIM];    // A lo
__device__ __half g_bh [(size_t)QKV_F * E_DIM];     // w_qkv fp16
__device__ __half g_ph [(size_t)E_DIM * E_DIM];     // w_proj fp16
// flash operands
__device__ __half g_qhi[(size_t)BH * S_LEN * DH];
__device__ __half g_qlo[(size_t)BH * S_LEN * DH];
__device__ __half g_kh [(size_t)BH * S_LEN * DH];
__device__ __half g_vt [(size_t)BH * DH * SPAD];    // V^T fp16 [bh][d][s]

__device__ __forceinline__ uint32_t smem_to_u32(const void* p) {
    uint32_t a;
    asm("{ .reg .u64 t; cvta.to.shared.u64 t, %1; cvt.u32.u64 %0, t; }" : "=r"(a) : "l"(p));
    return a;
}

// ---- mma.sync helpers (fp16 in, fp32 accum) ----
#define LDSM4(r, addr)                                                         \
    asm volatile("ldmatrix.sync.aligned.m8n8.x4.shared.b16 {%0,%1,%2,%3}, [%4];" \
        : "=r"((r)[0]), "=r"((r)[1]), "=r"((r)[2]), "=r"((r)[3]) : "r"(addr))

#define MMA16816(d, a, b0, b1)                                                 \
    asm volatile("mma.sync.aligned.m16n8k16.row.col.f32.f16.f16.f32 "          \
        "{%0,%1,%2,%3}, {%4,%5,%6,%7}, {%8,%9}, {%0,%1,%2,%3};"                \
        : "+f"((d)[0]), "+f"((d)[1]), "+f"((d)[2]), "+f"((d)[3])               \
        : "r"((a)[0]), "r"((a)[1]), "r"((a)[2]), "r"((a)[3]), "r"(b0), "r"(b1))

// 16B-chunk swizzles
#define CHUNK_OFF(row, c) (((row) << 6) + ((((c) ^ (((row) >> 1) & 3))) << 4)) // [r][32 h16]
#define CH8(row, c)       (((row) << 7) + ((((c) ^ ((row) & 7))) << 4))        // [r][64 h16]

__device__ __forceinline__ uint32_t pk2h(float f0, float f1) {
    __half2 h = __floats2half2_rn(f0, f1);
    return *(uint32_t*)&h;
}

// ======================= fp16 splits ========================================
__global__ __launch_bounds__(256) void split2_h(const float4* __restrict__ src,
                                                uint2* __restrict__ hi,
                                                uint2* __restrict__ lo, int n4)
{
    int i = blockIdx.x * blockDim.x + threadIdx.x;
    if (i >= n4) return;
    float4 v = src[i];
    __half h0 = __float2half_rn(v.x), h1 = __float2half_rn(v.y);
    __half h2 = __float2half_rn(v.z), h3 = __float2half_rn(v.w);
    uint2 hv, lv;
    hv.x = pk2h(v.x, v.y);
    hv.y = pk2h(v.z, v.w);
    lv.x = pk2h(v.x - __half2float(h0), v.y - __half2float(h1));
    lv.y = pk2h(v.z - __half2float(h2), v.w - __half2float(h3));
    hi[i] = hv;
    lo[i] = lv;
}

__global__ __launch_bounds__(256) void split1_h(const float4* __restrict__ src,
                                                uint2* __restrict__ dst, int n4)
{
    int i = blockIdx.x * blockDim.x + threadIdx.x;
    if (i >= n4) return;
    float4 v = src[i];
    uint2 o;
    o.x = pk2h(v.x, v.y);
    o.y = pk2h(v.z, v.w);
    dst[i] = o;
}

// ======================= HMMA GEMM (fp16x2, cp.async 3-stage, 2 CTA/SM) =====
#define GEMM_STAGE 24576
#define GEMM_SMEM  (3 * GEMM_STAGE)

template<bool QKV>
__global__ __launch_bounds__(256, 2) void mma_gemm(float* __restrict__ C,
                                                   const __half* __restrict__ Bh)
{
    extern __shared__ char sm[];
    const int tid  = threadIdx.x;
    const int lane = tid & 31;
    const int wid  = tid >> 5;
    const int wm   = wid & 3;
    const int wn   = wid >> 2;
    const int row0 = blockIdx.y * 128;
    const int col0 = blockIdx.x * 128;
    const uint32_t smem = smem_to_u32(sm);

    const int lr = tid >> 2;
    const int lc = tid & 3;

    const int arow[2] = { wm * 32 + 0 * 16 + (lane & 7) + ((lane >> 3) & 1) * 8,
                          wm * 32 + 1 * 16 + (lane & 7) + ((lane >> 3) & 1) * 8 };
    const int achk = lane >> 4;
    const int brow[4] = { wn * 64 + 0 * 16 + (lane & 7) + (lane >> 4) * 8,
                          wn * 64 + 1 * 16 + (lane & 7) + (lane >> 4) * 8,
                          wn * 64 + 2 * 16 + (lane & 7) + (lane >> 4) * 8,
                          wn * 64 + 3 * 16 + (lane & 7) + (lane >> 4) * 8 };
    const int bchk = (lane >> 3) & 1;

#define ISSUE(s_)                                                              \
    {                                                                          \
        uint32_t sb_ = smem + ((s_) % 3) * GEMM_STAGE;                         \
        int k0_ = (s_) * 32;                                                   \
        _Pragma("unroll")                                                      \
        for (int p = 0; p < 2; p++) {                                          \
            int r = lr + p * 64;                                               \
            int rA = row0 + r;                                                 \
            uint32_t szA = (rA < M_ROWS) ? 16u : 0u;                           \
            size_t offA = (size_t)(rA < M_ROWS ? rA : 0) * E_DIM + k0_ + lc * 8; \
            size_t offB = (size_t)(col0 + r) * E_DIM + k0_ + lc * 8;           \
            uint32_t co = CHUNK_OFF(r, lc);                                    \
            asm volatile("cp.async.cg.shared.global [%0], [%1], 16, %2;"       \
                :: "r"(sb_ + co), "l"(g_ahi + offA), "r"(szA));                \
            asm volatile("cp.async.cg.shared.global [%0], [%1], 16, %2;"       \
                :: "r"(sb_ + 8192 + co), "l"(g_alo + offA), "r"(szA));         \
            asm volatile("cp.async.cg.shared.global [%0], [%1], 16;"           \
                :: "r"(sb_ + 16384 + co), "l"(Bh + offB));                     \
        }                                                                      \
        asm volatile("cp.async.commit_group;");                                \
    }

    ISSUE(0)
    ISSUE(1)

    float acc[2][8][4] = {};

    for (int s = 0; s < 24; s++) {
        if (s + 1 < 24) asm volatile("cp.async.wait_group 1;");
        else            asm volatile("cp.async.wait_group 0;");
        __syncthreads();
        if (s + 2 < 24) ISSUE(s + 2)

        const uint32_t sb = smem + (s % 3) * GEMM_STAGE;
#pragma unroll
        for (int ks = 0; ks < 2; ks++) {
            uint32_t ah[2][4], al[2][4];
#pragma unroll
            for (int i = 0; i < 2; i++) {
                uint32_t adr = sb + CHUNK_OFF(arow[i], ks * 2 + achk);
                LDSM4(ah[i], adr);
                LDSM4(al[i], adr + 8192);
            }
            uint32_t bf[4][4];
#pragma unroll
            for (int g = 0; g < 4; g++) {
                uint32_t adr = sb + 16384 + CHUNK_OFF(brow[g], ks * 2 + bchk);
                LDSM4(bf[g], adr);
            }
#pragma unroll
            for (int i = 0; i < 2; i++)
#pragma unroll
                for (int g = 0; g < 4; g++)
#pragma unroll
                    for (int hh = 0; hh < 2; hh++)
                        MMA16816(acc[i][g*2+hh], ah[i], bf[g][hh*2], bf[g][hh*2+1]);
#pragma unroll
            for (int i = 0; i < 2; i++)
#pragma unroll
                for (int g = 0; g < 4; g++)
#pragma unroll
                    for (int hh = 0; hh < 2; hh++)
                        MMA16816(acc[i][g*2+hh], al[i], bf[g][hh*2], bf[g][hh*2+1]);
        }
    }
#undef ISSUE

#pragma unroll
    for (int i = 0; i < 2; i++)
#pragma unroll
        for (int half = 0; half < 2; half++) {
            int m = row0 + wm * 32 + i * 16 + (lane >> 2) + half * 8;
            if (m >= M_ROWS) continue;
            int bb = 0, sIdx = 0;
            if (QKV) { bb = m / S_LEN; sIdx = m - bb * S_LEN; }
#pragma unroll
            for (int j = 0; j < 8; j++) {
                int n = col0 + wn * 64 + j * 8 + (lane & 3) * 2;
                float2 v = make_float2(acc[i][j][half*2], acc[i][j][half*2+1]);
                if (QKV) {
                    int t = n / E_DIM, r = n - t * E_DIM;
                    int h = r >> 6, d = r & 63;
                    __half* dst = (t == 0) ? g_qpre : (t == 1) ? g_kpre : g_vpre;
                    size_t off = (((size_t)bb * NH + h) * S_LEN + sIdx) * DH + d;
                    *(uint32_t*)&dst[off] = pk2h(v.x, v.y);
                } else {
                    *(float2*)&C[(size_t)m * E_DIM + n] = v;
                }
            }
        }
}

// ======================= convert: rope (table) + fp16 prep ==================
__global__ __launch_bounds__(256) void convert_rope_split()
{
    const int bh    = blockIdx.y;
    const int chunk = blockIdx.x;
    const int s0    = chunk * 64;
    const int tid   = threadIdx.x;
    const int wid   = tid >> 5, lane = tid & 31;
    const unsigned full = 0xffffffffu;

    __shared__ float ct[24][16], st[24][16];
    for (int e = tid; e < 384; e += 256) {
        int v = e >> 4, f = e & 15;
        float dv = expf(-(float)(2 * f) * (9.210340371976184f / 32.0f));
        float a  = (float)v * (1.0f / 23.00000001f) * dv;
        ct[v][f] = cosf(a);
        st[v][f] = sinf(a);
    }
    __syncthreads();

    const int fi = lane >> 1;

#pragma unroll
    for (int t = 0; t < 2; t++) {
        const __half* srcp = t ? g_kpre : g_qpre;
#pragma unroll
        for (int ps = 0; ps < 8; ps++) {
            int s = s0 + ps * 8 + wid;
            float v0 = 0.f, v1 = 0.f;
            bool valid = (s < S_LEN);
            if (valid) {
                const __half* base = srcp + ((size_t)bh * S_LEN + s) * DH;
                v0 = __half2float(base[lane]);
                v1 = __half2float(base[lane + 32]);
            }
            float p0 = __shfl_sync(full, v0, (lane + 31) & 31);
            float p1 = __shfl_sync(full, v1, (lane + 31) & 31);
            if (valid && s > 0) {
                int p  = s - 1;
                int px = p % 24, py = p / 24;
                v0 = v0 * ct[px][fi] + p0 * st[px][fi];
                v1 = v1 * ct[py][fi] + p1 * st[py][fi];
            }
            if (valid) {
                size_t off = ((size_t)bh * S_LEN + s) * DH;
                if (t == 0) {
                    __half h0 = __float2half_rn(v0);
                    __half h1 = __float2half_rn(v1);
                    g_qhi[off + lane]      = h0;
                    g_qhi[off + lane + 32] = h1;
                    g_qlo[off + lane]      = __float2half_rn(v0 - __half2float(h0));
                    g_qlo[off + lane + 32] = __float2half_rn(v1 - __half2float(h1));
                } else {
                    g_kh[off + lane]      = __float2half_rn(v0);
                    g_kh[off + lane + 32] = __float2half_rn(v1);
                }
            }
        }
    }

    // V transpose -> g_vt fp16 [bh][d][s0..s0+64) (zeros beyond S_LEN)
    __shared__ float vbuf[64][65];
#pragma unroll
    for (int it = 0; it < 16; it++) {
        int idx = tid + it * 256;
        int r = idx >> 6, c = idx & 63;
        float val = (s0 + r < S_LEN)
            ? __half2float(g_vpre[((size_t)bh * S_LEN + s0 + r) * DH + c]) : 0.f;
        vbuf[c][r] = val;
    }
    __syncthreads();
    {
        int d = tid >> 2, grp = tid & 3;
        __half hh[16];
#pragma unroll
        for (int i = 0; i < 16; i++)
            hh[i] = __float2half_rn(vbuf[d][grp * 16 + i]);
        size_t dst = (size_t)bh * (DH * SPAD) + (size_t)d * SPAD + s0 + grp * 16;
        *(uint4*)(g_vt + dst)     = *(uint4*)hh;
        *(uint4*)(g_vt + dst + 8) = *(uint4*)(hh + 8);
    }
}

// ======================= HMMA flash attention (fp16x2, 48KB, 2 CTA/SM) ======
#define FLASH_SMEM 49152

__global__ __launch_bounds__(256, 2) void flash_mma()
{
    extern __shared__ char sm[];
    const uint32_t smem = smem_to_u32(sm);

    const int bh  = blockIdx.y;
    const int i0  = blockIdx.x * 128;
    const int tid = threadIdx.x;
    const int lane = tid & 31, wid = tid >> 5;

#define KVBASE(t_) (smem + (((t_) & 1) ? 0u : 32768u))

#define ISSUE_KV(t_)                                                           \
    {                                                                          \
        uint32_t kb_ = KVBASE(t_);                                             \
        int j0_ = (t_) * 64;                                                   \
        _Pragma("unroll")                                                      \
        for (int it = 0; it < 2; it++) {                                       \
            int idx = tid + it * 256;                                          \
            int r = idx >> 3, c = idx & 7;                                     \
            int sj = j0_ + r;                                                  \
            uint32_t szK = (sj < S_LEN) ? 16u : 0u;                            \
            size_t koff = ((size_t)bh * S_LEN + (sj < S_LEN ? sj : 0)) * DH + c * 8; \
            size_t voff = (size_t)bh * (DH * SPAD) + (size_t)r * SPAD + j0_ + c * 8; \
            uint32_t co = CH8(r, c);                                           \
            asm volatile("cp.async.cg.shared.global [%0], [%1], 16, %2;"       \
                :: "r"(kb_ + co), "l"(g_kh + koff), "r"(szK));                 \
            asm volatile("cp.async.cg.shared.global [%0], [%1], 16;"           \
                :: "r"(kb_ + 8192 + co), "l"(g_vt + voff));                    \
        }                                                                      \
        asm volatile("cp.async.commit_group;");                                \
    }

    ISSUE_KV(0)

#pragma unroll
    for (int it = 0; it < 4; it++) {
        int idx = tid + it * 256;
        int r = idx >> 3, c = idx & 7;
        int s = i0 + r;
        uint4 vh = make_uint4(0u,0u,0u,0u), vl = vh;
        if (s < S_LEN) {
            size_t off = ((size_t)bh * S_LEN + s) * DH + c * 8;
            vh = *(const uint4*)(g_qhi + off);
            vl = *(const uint4*)(g_qlo + off);
        }
        *(uint4*)(sm + CH8(r, c)) = vh;
        *(uint4*)(sm + 16384 + CH8(r, c)) = vl;
    }
    __syncthreads();

    uint32_t qhf[4][4], qlf[4][4];
    {
        const int ar = wid * 16 + (lane & 7) + ((lane >> 3) & 1) * 8;
        const int ac = lane >> 4;
#pragma unroll
        for (int kt = 0; kt < 4; kt++) {
            LDSM4(qhf[kt], smem + CH8(ar, kt * 2 + ac));
            LDSM4(qlf[kt], smem + 16384 + CH8(ar, kt * 2 + ac));
        }
    }
    __syncthreads();

    ISSUE_KV(1)

    float oacc[8][4] = {};
    float m0 = -1e30f, m1 = -1e30f, l0 = 0.f, l1 = 0.f;

    const int br = (lane & 7) + ((lane >> 4) << 3);
    const int bc = (lane >> 3) & 1;

    for (int t = 0; t < 10; t++) {
        const int j0 = t * 64;
        if (t < 8) asm volatile("cp.async.wait_group 1;");
        else       asm volatile("cp.async.wait_group 0;");
        __syncthreads();

        const uint32_t kvb  = KVBASE(t);
        const uint32_t kh32 = kvb, vh32 = kvb + 8192;

        float sacc[8][4] = {};
#pragma unroll
        for (int kt = 0; kt < 4; kt++) {
            uint32_t khf[4][4];
#pragma unroll
            for (int g = 0; g < 4; g++)
                LDSM4(khf[g], kh32 + CH8(g * 16 + br, kt * 2 + bc));
#pragma unroll
            for (int g = 0; g < 4; g++)
#pragma unroll
                for (int hh = 0; hh < 2; hh++)
                    MMA16816(sacc[g*2+hh], qhf[kt], khf[g][hh*2], khf[g][hh*2+1]);
#pragma unroll
            for (int g = 0; g < 4; g++)
#pragma unroll
                for (int hh = 0; hh < 2; hh++)
                    MMA16816(sacc[g*2+hh], qlf[kt], khf[g][hh*2], khf[g][hh*2+1]);
        }

        float tm0 = -1e30f, tm1 = -1e30f;
#pragma unroll
        for (int nt = 0; nt < 8; nt++) {
            int jb = j0 + nt * 8 + (lane & 3) * 2;
            sacc[nt][0] = (jb     < S_LEN) ? sacc[nt][0] * 0.125f : -1e30f;
            sacc[nt][1] = (jb + 1 < S_LEN) ? sacc[nt][1] * 0.125f : -1e30f;
            sacc[nt][2] = (jb     < S_LEN) ? sacc[nt][2] * 0.125f : -1e30f;
            sacc[nt][3] = (jb + 1 < S_LEN) ? sacc[nt][3] * 0.125f : -1e30f;
            tm0 = fmaxf(tm0, fmaxf(sacc[nt][0], sacc[nt][1]));
            tm1 = fmaxf(tm1, fmaxf(sacc[nt][2], sacc[nt][3]));
        }
        tm0 = fmaxf(tm0, __shfl_xor_sync(0xffffffffu, tm0, 1));
        tm0 = fmaxf(tm0, __shfl_xor_sync(0xffffffffu, tm0, 2));
        tm1 = fmaxf(tm1, __shfl_xor_sync(0xffffffffu, tm1, 1));
        tm1 = fmaxf(tm1, __shfl_xor_sync(0xffffffffu, tm1, 2));
        float mn0 = fmaxf(m0, tm0), mn1 = fmaxf(m1, tm1);
        float f0 = __expf(m0 - mn0), f1 = __expf(m1 - mn1);
        m0 = mn0; m1 = mn1;

        float rs0 = 0.f, rs1 = 0.f;
#pragma unroll
        for (int nt = 0; nt < 8; nt++) {
            sacc[nt][0] = __expf(sacc[nt][0] - mn0);
            sacc[nt][1] = __expf(sacc[nt][1] - mn0);
            sacc[nt][2] = __expf(sacc[nt][2] - mn1);
            sacc[nt][3] = __expf(sacc[nt][3] - mn1);
            rs0 += sacc[nt][0] + sacc[nt][1];
            rs1 += sacc[nt][2] + sacc[nt][3];
        }
        rs0 += __shfl_xor_sync(0xffffffffu, rs0, 1);
        rs0 += __shfl_xor_sync(0xffffffffu, rs0, 2);
        rs1 += __shfl_xor_sync(0xffffffffu, rs1, 1);
        rs1 += __shfl_xor_sync(0xffffffffu, rs1, 2);
        l0 = l0 * f0 + rs0;
        l1 = l1 * f1 + rs1;

#pragma unroll
        for (int nt = 0; nt < 8; nt++) {
            oacc[nt][0] *= f0; oacc[nt][1] *= f0;
            oacc[nt][2] *= f1; oacc[nt][3] *= f1;
        }

        uint32_t pahi[4][4], palo[4][4];
#pragma unroll
        for (int kt = 0; kt < 4; kt++) {
            const int t0 = kt * 2, t1 = kt * 2 + 1;
            float v00 = sacc[t0][0], v01 = sacc[t0][1];
            float v02 = sacc[t0][2], v03 = sacc[t0][3];
            float v10 = sacc[t1][0], v11 = sacc[t1][1];
            float v12 = sacc[t1][2], v13 = sacc[t1][3];
            pahi[kt][0] = pk2h(v00, v01);
            pahi[kt][1] = pk2h(v02, v03);
            pahi[kt][2] = pk2h(v10, v11);
            pahi[kt][3] = pk2h(v12, v13);
            palo[kt][0] = pk2h(v00 - __half2float(__float2half_rn(v00)),
                               v01 - __half2float(__float2half_rn(v01)));
            palo[kt][1] = pk2h(v02 - __half2float(__float2half_rn(v02)),
                               v03 - __half2float(__float2half_rn(v03)));
            palo[kt][2] = pk2h(v10 - __half2float(__float2half_rn(v10)),
                               v11 - __half2float(__float2half_rn(v11)));
            palo[kt][3] = pk2h(v12 - __half2float(__float2half_rn(v12)),
                               v13 - __half2float(__float2half_rn(v13)));
        }

#pragma unroll
        for (int kt = 0; kt < 4; kt++) {
            uint32_t vhf[4][4];
#pragma unroll
            for (int g = 0; g < 4; g++)
                LDSM4(vhf[g], vh32 + CH8(g * 16 + br, kt * 2 + bc));
#pragma unroll
            for (int g = 0; g < 4; g++)
#pragma unroll
                for (int hh = 0; hh < 2; hh++)
                    MMA16816(oacc[g*2+hh], pahi[kt], vhf[g][hh*2], vhf[g][hh*2+1]);
#pragma unroll
            for (int g = 0; g < 4; g++)
#pragma unroll
                for (int hh = 0; hh < 2; hh++)
                    MMA16816(oacc[g*2+hh], palo[kt], vhf[g][hh*2], vhf[g][hh*2+1]);
        }
        __syncthreads();
        if (t + 2 < 10) ISSUE_KV(t + 2)
    }
#undef ISSUE_KV
#undef KVBASE

    // epilogue: ctx as fp16 hi/lo into g_ahi/g_alo (A of out-proj GEMM)
    const float inv0 = 1.f / l0, inv1 = 1.f / l1;
    const int b = bh / NH, h = bh % NH;
    const int r0 = i0 + wid * 16 + (lane >> 2);
    const int r1 = r0 + 8;
#pragma unroll
    for (int nt = 0; nt < 8; nt++) {
        int d = nt * 8 + (lane & 3) * 2;
        if (r0 < S_LEN) {
            float o0 = oacc[nt][0] * inv0, o1 = oacc[nt][1] * inv0;
            size_t off = ((size_t)b * S_LEN + r0) * E_DIM + h * DH + d;
            *(uint32_t*)&g_ahi[off] = pk2h(o0, o1);
            *(uint32_t*)&g_alo[off] = pk2h(o0 - __half2float(__float2half_rn(o0)),
                                           o1 - __half2float(__float2half_rn(o1)));
        }
        if (r1 < S_LEN) {
            float o2 = oacc[nt][2] * inv1, o3 = oacc[nt][3] * inv1;
            size_t off = ((size_t)b * S_LEN + r1) * E_DIM + h * DH + d;
            *(uint32_t*)&g_ahi[off] = pk2h(o2, o3);
            *(uint32_t*)&g_alo[off] = pk2h(o2 - __half2float(__float2half_rn(o2)),
                                           o3 - __half2float(__float2half_rn(o3)));
        }
    }
}

// ======================= launch =============================================
extern "C" void kernel_launch(void* const* d_in, const int* in_sizes, int n_in,
                              void* d_out, int out_size)
{
    (void)in_sizes; (void)n_in; (void)out_size;
    const float* x      = (const float*)d_in[0];
    const float* w_qkv  = (const float*)d_in[1];
    const float* w_proj = (const float*)d_in[2];
    float* out = (float*)d_out;

    void *ahi, *alo, *bh, *ph;
    cudaGetSymbolAddress(&ahi, g_ahi);
    cudaGetSymbolAddress(&alo, g_alo);
    cudaGetSymbolAddress(&bh, g_bh);
    cudaGetSymbolAddress(&ph, g_ph);

    cudaFuncSetAttribute(mma_gemm<true>,  cudaFuncAttributeMaxDynamicSharedMemorySize, GEMM_SMEM);
    cudaFuncSetAttribute(mma_gemm<false>, cudaFuncAttributeMaxDynamicSharedMemorySize, GEMM_SMEM);
    cudaFuncSetAttribute(flash_mma, cudaFuncAttributeMaxDynamicSharedMemorySize, FLASH_SMEM);

    const int MT = (M_ROWS + 127) / 128;   // 145

    // 1) input conversions up front
    {
        int n4 = M_ROWS * E_DIM / 4;
        split2_h<<<(n4 + 255) / 256, 256>>>((const float4*)x, (uint2*)ahi, (uint2*)alo, n4);
        int w4 = QKV_F * E_DIM / 4;
        split1_h<<<(w4 + 255) / 256, 256>>>((const float4*)w_qkv, (uint2*)bh, w4);
        int p4 = E_DIM * E_DIM / 4;
        split1_h<<<(p4 + 255) / 256, 256>>>((const float4*)w_proj, (uint2*)ph, p4);
    }

    // 2) QKV projection -> q,k,v fp16 in g_qpre/g_kpre/g_vpre
    mma_gemm<true><<<dim3(QKV_F / 128, MT), 256, GEMM_SMEM>>>(
        nullptr, (const __half*)bh);

    // 3) rope (table) + fp16 prep of q (hi/lo), k (single), V^T (single)
    convert_rope_split<<<dim3(10, BH), 256>>>();

    // 4) HMMA flash attention -> ctx as fp16 hi/lo into g_ahi/g_alo
    flash_mma<<<dim3(5, BH), 256, FLASH_SMEM>>>();

    // 5) output projection
    mma_gemm<false><<<dim3(E_DIM / 128, MT), 256, GEMM_SMEM>>>(
        out, (const __half*)ph);
}

// round 16
// speedup vs baseline: 1.7733x; 1.2737x over previous
#include <cuda_runtime.h>
#include <cuda_fp16.h>
#include <math.h>
#include <stdint.h>

#define B_SZ   32
#define S_LEN  577
#define E_DIM  768
#define NH     12
#define DH     64
#define BH     (B_SZ * NH)         // 384
#define M_ROWS (B_SZ * S_LEN)      // 18464
#define QKV_F  (3 * E_DIM)         // 2304
#define SPAD   640
#define HSTRIDE ((size_t)BH * S_LEN * DH)

// Scratch (device globals; allocation-free per harness rules)
__device__ __half g_qpre[(size_t)BH * S_LEN * DH];  // pre-rope q fp16 [bh][s][d]
__device__ __half g_kpre[(size_t)BH * S_LEN * DH];  // pre-rope k fp16
__device__ __half g_vpre[(size_t)BH * S_LEN * DH];  // v fp16
__device__ __half g_ahi[(size_t)M_ROWS * E_DIM];    // A hi (x fp16, then ctx hi)
__device__ __half g_alo[(size_t)M_ROWS * E_DIM];    // A lo (ctx lo only)
__device__ __half g_bh [(size_t)QKV_F * E_DIM];     // w_qkv fp16
__device__ __half g_ph [(size_t)E_DIM * E_DIM];     // w_proj fp16
// flash operands
__device__ __half g_qh [(size_t)BH * S_LEN * DH];   // roped q fp16 (single)
__device__ __half g_kh [(size_t)BH * S_LEN * DH];   // roped k fp16
__device__ __half g_vt [(size_t)BH * DH * SPAD];    // V^T fp16 [bh][d][s]

__device__ __forceinline__ uint32_t smem_to_u32(const void* p) {
    uint32_t a;
    asm("{ .reg .u64 t; cvta.to.shared.u64 t, %1; cvt.u32.u64 %0, t; }" : "=r"(a) : "l"(p));
    return a;
}

// ---- mma.sync helpers (fp16 in, fp32 accum) ----
#define LDSM4(r, addr)                                                         \
    asm volatile("ldmatrix.sync.aligned.m8n8.x4.shared.b16 {%0,%1,%2,%3}, [%4];" \
        : "=r"((r)[0]), "=r"((r)[1]), "=r"((r)[2]), "=r"((r)[3]) : "r"(addr))

#define MMA16816(d, a, b0, b1)                                                 \
    asm volatile("mma.sync.aligned.m16n8k16.row.col.f32.f16.f16.f32 "          \
        "{%0,%1,%2,%3}, {%4,%5,%6,%7}, {%8,%9}, {%0,%1,%2,%3};"                \
        : "+f"((d)[0]), "+f"((d)[1]), "+f"((d)[2]), "+f"((d)[3])               \
        : "r"((a)[0]), "r"((a)[1]), "r"((a)[2]), "r"((a)[3]), "r"(b0), "r"(b1))

// 16B-chunk swizzles
#define CHUNK_OFF(row, c) (((row) << 6) + ((((c) ^ (((row) >> 1) & 3))) << 4)) // [r][32 h16]
#define CH8(row, c)       (((row) << 7) + ((((c) ^ ((row) & 7))) << 4))        // [r][64 h16]

__device__ __forceinline__ uint32_t pk2h(float f0, float f1) {
    __half2 h = __floats2half2_rn(f0, f1);
    return *(uint32_t*)&h;
}

// ======================= fp16 splits ========================================
__global__ __launch_bounds__(256) void split1_h(const float4* __restrict__ src,
                                                uint2* __restrict__ dst, int n4)
{
    int i = blockIdx.x * blockDim.x + threadIdx.x;
    if (i >= n4) return;
    float4 v = src[i];
    uint2 o;
    o.x = pk2h(v.x, v.y);
    o.y = pk2h(v.z, v.w);
    dst[i] = o;
}

// ======================= HMMA GEMM (cp.async 3-stage, 2 CTA/SM) =============
// ALO=true: C = (Ahi+Alo) @ B^T (two MMA passes); ALO=false: C = Ahi @ B^T.
#define GEMM_STAGE 24576
#define GEMM_SMEM  (3 * GEMM_STAGE)

template<bool QKV, bool ALO>
__global__ __launch_bounds__(256, 2) void mma_gemm(float* __restrict__ C,
                                                   const __half* __restrict__ Bh)
{
    extern __shared__ char sm[];
    const int tid  = threadIdx.x;
    const int lane = tid & 31;
    const int wid  = tid >> 5;
    const int wm   = wid & 3;
    const int wn   = wid >> 2;
    const int row0 = blockIdx.y * 128;
    const int col0 = blockIdx.x * 128;
    const uint32_t smem = smem_to_u32(sm);

    const int lr = tid >> 2;
    const int lc = tid & 3;

    const int arow[2] = { wm * 32 + 0 * 16 + (lane & 7) + ((lane >> 3) & 1) * 8,
                          wm * 32 + 1 * 16 + (lane & 7) + ((lane >> 3) & 1) * 8 };
    const int achk = lane >> 4;
    const int brow[4] = { wn * 64 + 0 * 16 + (lane & 7) + (lane >> 4) * 8,
                          wn * 64 + 1 * 16 + (lane & 7) + (lane >> 4) * 8,
                          wn * 64 + 2 * 16 + (lane & 7) + (lane >> 4) * 8,
                          wn * 64 + 3 * 16 + (lane & 7) + (lane >> 4) * 8 };
    const int bchk = (lane >> 3) & 1;

#define ISSUE(s_)                                                              \
    {                                                                          \
        uint32_t sb_ = smem + ((s_) % 3) * GEMM_STAGE;                         \
        int k0_ = (s_) * 32;                                                   \
        _Pragma("unroll")                                                      \
        for (int p = 0; p < 2; p++) {                                          \
            int r = lr + p * 64;                                               \
            int rA = row0 + r;                                                 \
            uint32_t szA = (rA < M_ROWS) ? 16u : 0u;                           \
            size_t offA = (size_t)(rA < M_ROWS ? rA : 0) * E_DIM + k0_ + lc * 8; \
            size_t offB = (size_t)(col0 + r) * E_DIM + k0_ + lc * 8;           \
            uint32_t co = CHUNK_OFF(r, lc);                                    \
            asm volatile("cp.async.cg.shared.global [%0], [%1], 16, %2;"       \
                :: "r"(sb_ + co), "l"(g_ahi + offA), "r"(szA));                \
            if (ALO)                                                           \
                asm volatile("cp.async.cg.shared.global [%0], [%1], 16, %2;"   \
                    :: "r"(sb_ + 8192 + co), "l"(g_alo + offA), "r"(szA));     \
            asm volatile("cp.async.cg.shared.global [%0], [%1], 16;"           \
                :: "r"(sb_ + 16384 + co), "l"(Bh + offB));                     \
        }                                                                      \
        asm volatile("cp.async.commit_group;");                                \
    }

    ISSUE(0)
    ISSUE(1)

    float acc[2][8][4] = {};

    for (int s = 0; s < 24; s++) {
        if (s + 1 < 24) asm volatile("cp.async.wait_group 1;");
        else            asm volatile("cp.async.wait_group 0;");
        __syncthreads();
        if (s + 2 < 24) ISSUE(s + 2)

        const uint32_t sb = smem + (s % 3) * GEMM_STAGE;
#pragma unroll
        for (int ks = 0; ks < 2; ks++) {
            uint32_t ah[2][4], al[2][4];
#pragma unroll
            for (int i = 0; i < 2; i++) {
                uint32_t adr = sb + CHUNK_OFF(arow[i], ks * 2 + achk);
                LDSM4(ah[i], adr);
                if (ALO) LDSM4(al[i], adr + 8192);
            }
            uint32_t bf[4][4];
#pragma unroll
            for (int g = 0; g < 4; g++) {
                uint32_t adr = sb + 16384 + CHUNK_OFF(brow[g], ks * 2 + bchk);
                LDSM4(bf[g], adr);
            }
#pragma unroll
            for (int i = 0; i < 2; i++)
#pragma unroll
                for (int g = 0; g < 4; g++)
#pragma unroll
                    for (int hh = 0; hh < 2; hh++)
                        MMA16816(acc[i][g*2+hh], ah[i], bf[g][hh*2], bf[g][hh*2+1]);
            if (ALO) {
#pragma unroll
                for (int i = 0; i < 2; i++)
#pragma unroll
                    for (int g = 0; g < 4; g++)
#pragma unroll
                        for (int hh = 0; hh < 2; hh++)
                            MMA16816(acc[i][g*2+hh], al[i], bf[g][hh*2], bf[g][hh*2+1]);
            }
        }
    }
#undef ISSUE

#pragma unroll
    for (int i = 0; i < 2; i++)
#pragma unroll
        for (int half = 0; half < 2; half++) {
            int m = row0 + wm * 32 + i * 16 + (lane >> 2) + half * 8;
            if (m >= M_ROWS) continue;
            int bb = 0, sIdx = 0;
            if (QKV) { bb = m / S_LEN; sIdx = m - bb * S_LEN; }
#pragma unroll
            for (int j = 0; j < 8; j++) {
                int n = col0 + wn * 64 + j * 8 + (lane & 3) * 2;
                float2 v = make_float2(acc[i][j][half*2], acc[i][j][half*2+1]);
                if (QKV) {
                    int t = n / E_DIM, r = n - t * E_DIM;
                    int h = r >> 6, d = r & 63;
                    __half* dst = (t == 0) ? g_qpre : (t == 1) ? g_kpre : g_vpre;
                    size_t off = (((size_t)bb * NH + h) * S_LEN + sIdx) * DH + d;
                    *(uint32_t*)&dst[off] = pk2h(v.x, v.y);
                } else {
                    *(float2*)&C[(size_t)m * E_DIM + n] = v;
                }
            }
        }
}

// ======================= convert: rope (table) + fp16 prep ==================
__global__ __launch_bounds__(256) void convert_rope_split()
{
    const int bh    = blockIdx.y;
    const int chunk = blockIdx.x;
    const int s0    = chunk * 64;
    const int tid   = threadIdx.x;
    const int wid   = tid >> 5, lane = tid & 31;
    const unsigned full = 0xffffffffu;

    __shared__ float ct[24][16], st[24][16];
    for (int e = tid; e < 384; e += 256) {
        int v = e >> 4, f = e & 15;
        float dv = expf(-(float)(2 * f) * (9.210340371976184f / 32.0f));
        float a  = (float)v * (1.0f / 23.00000001f) * dv;
        ct[v][f] = cosf(a);
        st[v][f] = sinf(a);
    }
    __syncthreads();

    const int fi = lane >> 1;

#pragma unroll
    for (int t = 0; t < 2; t++) {
        const __half* srcp = t ? g_kpre : g_qpre;
        __half* dstp = t ? g_kh : g_qh;
#pragma unroll
        for (int ps = 0; ps < 8; ps++) {
            int s = s0 + ps * 8 + wid;
            float v0 = 0.f, v1 = 0.f;
            bool valid = (s < S_LEN);
            if (valid) {
                const __half* base = srcp + ((size_t)bh * S_LEN + s) * DH;
                v0 = __half2float(base[lane]);
                v1 = __half2float(base[lane + 32]);
            }
            float p0 = __shfl_sync(full, v0, (lane + 31) & 31);
            float p1 = __shfl_sync(full, v1, (lane + 31) & 31);
            if (valid && s > 0) {
                int p  = s - 1;
                int px = p % 24, py = p / 24;
                v0 = v0 * ct[px][fi] + p0 * st[px][fi];
                v1 = v1 * ct[py][fi] + p1 * st[py][fi];
            }
            if (valid) {
                size_t off = ((size_t)bh * S_LEN + s) * DH;
                dstp[off + lane]      = __float2half_rn(v0);
                dstp[off + lane + 32] = __float2half_rn(v1);
            }
        }
    }

    // V transpose -> g_vt fp16 [bh][d][s0..s0+64) (zeros beyond S_LEN)
    __shared__ float vbuf[64][65];
#pragma unroll
    for (int it = 0; it < 16; it++) {
        int idx = tid + it * 256;
        int r = idx >> 6, c = idx & 63;
        float val = (s0 + r < S_LEN)
            ? __half2float(g_vpre[((size_t)bh * S_LEN + s0 + r) * DH + c]) : 0.f;
        vbuf[c][r] = val;
    }
    __syncthreads();
    {
        int d = tid >> 2, grp = tid & 3;
        __half hh[16];
#pragma unroll
        for (int i = 0; i < 16; i++)
            hh[i] = __float2half_rn(vbuf[d][grp * 16 + i]);
        size_t dst = (size_t)bh * (DH * SPAD) + (size_t)d * SPAD + s0 + grp * 16;
        *(uint4*)(g_vt + dst)     = *(uint4*)hh;
        *(uint4*)(g_vt + dst + 8) = *(uint4*)(hh + 8);
    }
}

// ======================= HMMA flash attention (fp16, 32KB, 2 CTA/SM) ========
// Q staging @[0,16K); KV tile 16KB: even -> @16384, odd -> @0 (ex-Q).
#define FLASH_SMEM 32768

__global__ __launch_bounds__(256, 2) void flash_mma()
{
    extern __shared__ char sm[];
    const uint32_t smem = smem_to_u32(sm);

    const int bh  = blockIdx.y;
    const int i0  = blockIdx.x * 128;
    const int tid = threadIdx.x;
    const int lane = tid & 31, wid = tid >> 5;

#define KVBASE(t_) (smem + (((t_) & 1) ? 0u : 16384u))

#define ISSUE_KV(t_)                                                           \
    {                                                                          \
        uint32_t kb_ = KVBASE(t_);                                             \
        int j0_ = (t_) * 64;                                                   \
        _Pragma("unroll")                                                      \
        for (int it = 0; it < 2; it++) {                                       \
            int idx = tid + it * 256;                                          \
            int r = idx >> 3, c = idx & 7;                                     \
            int sj = j0_ + r;                                                  \
            uint32_t szK = (sj < S_LEN) ? 16u : 0u;                            \
            size_t koff = ((size_t)bh * S_LEN + (sj < S_LEN ? sj : 0)) * DH + c * 8; \
            size_t voff = (size_t)bh * (DH * SPAD) + (size_t)r * SPAD + j0_ + c * 8; \
            uint32_t co = CH8(r, c);                                           \
            asm volatile("cp.async.cg.shared.global [%0], [%1], 16, %2;"       \
                :: "r"(kb_ + co), "l"(g_kh + koff), "r"(szK));                 \
            asm volatile("cp.async.cg.shared.global [%0], [%1], 16;"           \
                :: "r"(kb_ + 8192 + co), "l"(g_vt + voff));                    \
        }                                                                      \
        asm volatile("cp.async.commit_group;");                                \
    }

    ISSUE_KV(0)

    // Q staging (single fp16) into [0,16K)
#pragma unroll
    for (int it = 0; it < 4; it++) {
        int idx = tid + it * 256;
        int r = idx >> 3, c = idx & 7;
        int s = i0 + r;
        uint4 vh = make_uint4(0u,0u,0u,0u);
        if (s < S_LEN)
            vh = *(const uint4*)(g_qh + ((size_t)bh * S_LEN + s) * DH + c * 8);
        *(uint4*)(sm + CH8(r, c)) = vh;
    }
    __syncthreads();

    uint32_t qhf[4][4];
    {
        const int ar = wid * 16 + (lane & 7) + ((lane >> 3) & 1) * 8;
        const int ac = lane >> 4;
#pragma unroll
        for (int kt = 0; kt < 4; kt++)
            LDSM4(qhf[kt], smem + CH8(ar, kt * 2 + ac));
    }
    __syncthreads();   // Q reads done before KV(1) overwrites region

    ISSUE_KV(1)

    float oacc[8][4] = {};
    float m0 = -1e30f, m1 = -1e30f, l0 = 0.f, l1 = 0.f;

    const int br = (lane & 7) + ((lane >> 4) << 3);
    const int bc = (lane >> 3) & 1;

    for (int t = 0; t < 10; t++) {
        const int j0 = t * 64;
        if (t < 8) asm volatile("cp.async.wait_group 1;");
        else       asm volatile("cp.async.wait_group 0;");
        __syncthreads();

        const uint32_t kvb  = KVBASE(t);
        const uint32_t kh32 = kvb, vh32 = kvb + 8192;

        float sacc[8][4] = {};
#pragma unroll
        for (int kt = 0; kt < 4; kt++) {
            uint32_t khf[4][4];
#pragma unroll
            for (int g = 0; g < 4; g++)
                LDSM4(khf[g], kh32 + CH8(g * 16 + br, kt * 2 + bc));
#pragma unroll
            for (int g = 0; g < 4; g++)
#pragma unroll
                for (int hh = 0; hh < 2; hh++)
                    MMA16816(sacc[g*2+hh], qhf[kt], khf[g][hh*2], khf[g][hh*2+1]);
        }

        float tm0 = -1e30f, tm1 = -1e30f;
#pragma unroll
        for (int nt = 0; nt < 8; nt++) {
            int jb = j0 + nt * 8 + (lane & 3) * 2;
            sacc[nt][0] = (jb     < S_LEN) ? sacc[nt][0] * 0.125f : -1e30f;
            sacc[nt][1] = (jb + 1 < S_LEN) ? sacc[nt][1] * 0.125f : -1e30f;
            sacc[nt][2] = (jb     < S_LEN) ? sacc[nt][2] * 0.125f : -1e30f;
            sacc[nt][3] = (jb + 1 < S_LEN) ? sacc[nt][3] * 0.125f : -1e30f;
            tm0 = fmaxf(tm0, fmaxf(sacc[nt][0], sacc[nt][1]));
            tm1 = fmaxf(tm1, fmaxf(sacc[nt][2], sacc[nt][3]));
        }
        tm0 = fmaxf(tm0, __shfl_xor_sync(0xffffffffu, tm0, 1));
        tm0 = fmaxf(tm0, __shfl_xor_sync(0xffffffffu, tm0, 2));
        tm1 = fmaxf(tm1, __shfl_xor_sync(0xffffffffu, tm1, 1));
        tm1 = fmaxf(tm1, __shfl_xor_sync(0xffffffffu, tm1, 2));
        float mn0 = fmaxf(m0, tm0), mn1 = fmaxf(m1, tm1);
        float f0 = __expf(m0 - mn0), f1 = __expf(m1 - mn1);
        m0 = mn0; m1 = mn1;

        float rs0 = 0.f, rs1 = 0.f;
#pragma unroll
        for (int nt = 0; nt < 8; nt++) {
            sacc[nt][0] = __expf(sacc[nt][0] - mn0);
            sacc[nt][1] = __expf(sacc[nt][1] - mn0);
            sacc[nt][2] = __expf(sacc[nt][2] - mn1);
            sacc[nt][3] = __expf(sacc[nt][3] - mn1);
            rs0 += sacc[nt][0] + sacc[nt][1];
            rs1 += sacc[nt][2] + sacc[nt][3];
        }
        rs0 += __shfl_xor_sync(0xffffffffu, rs0, 1);
        rs0 += __shfl_xor_sync(0xffffffffu, rs0, 2);
        rs1 += __shfl_xor_sync(0xffffffffu, rs1, 1);
        rs1 += __shfl_xor_sync(0xffffffffu, rs1, 2);
        l0 = l0 * f0 + rs0;
        l1 = l1 * f1 + rs1;

#pragma unroll
        for (int nt = 0; nt < 8; nt++) {
            oacc[nt][0] *= f0; oacc[nt][1] *= f0;
            oacc[nt][2] *= f1; oacc[nt][3] *= f1;
        }

        // P -> fp16 hi + residual lo (direct output path: keep both)
        uint32_t pahi[4][4], palo[4][4];
#pragma unroll
        for (int kt = 0; kt < 4; kt++) {
            const int t0 = kt * 2, t1 = kt * 2 + 1;
            float v00 = sacc[t0][0], v01 = sacc[t0][1];
            float v02 = sacc[t0][2], v03 = sacc[t0][3];
            float v10 = sacc[t1][0], v11 = sacc[t1][1];
            float v12 = sacc[t1][2], v13 = sacc[t1][3];
            pahi[kt][0] = pk2h(v00, v01);
            pahi[kt][1] = pk2h(v02, v03);
            pahi[kt][2] = pk2h(v10, v11);
            pahi[kt][3] = pk2h(v12, v13);
            palo[kt][0] = pk2h(v00 - __half2float(__float2half_rn(v00)),
                               v01 - __half2float(__float2half_rn(v01)));
            palo[kt][1] = pk2h(v02 - __half2float(__float2half_rn(v02)),
                               v03 - __half2float(__float2half_rn(v03)));
            palo[kt][2] = pk2h(v10 - __half2float(__float2half_rn(v10)),
                               v11 - __half2float(__float2half_rn(v11)));
            palo[kt][3] = pk2h(v12 - __half2float(__float2half_rn(v12)),
                               v13 - __half2float(__float2half_rn(v13)));
        }

#pragma unroll
        for (int kt = 0; kt < 4; kt++) {
            uint32_t vhf[4][4];
#pragma unroll
            for (int g = 0; g < 4; g++)
                LDSM4(vhf[g], vh32 + CH8(g * 16 + br, kt * 2 + bc));
#pragma unroll
            for (int g = 0; g < 4; g++)
#pragma unroll
                for (int hh = 0; hh < 2; hh++)
                    MMA16816(oacc[g*2+hh], pahi[kt], vhf[g][hh*2], vhf[g][hh*2+1]);
#pragma unroll
            for (int g = 0; g < 4; g++)
#pragma unroll
                for (int hh = 0; hh < 2; hh++)
                    MMA16816(oacc[g*2+hh], palo[kt], vhf[g][hh*2], vhf[g][hh*2+1]);
        }
        __syncthreads();
        if (t + 2 < 10) ISSUE_KV(t + 2)
    }
#undef ISSUE_KV
#undef KVBASE

    // epilogue: ctx as fp16 hi/lo into g_ahi/g_alo (A of out-proj GEMM)
    const float inv0 = 1.f / l0, inv1 = 1.f / l1;
    const int b = bh / NH, h = bh % NH;
    const int r0 = i0 + wid * 16 + (lane >> 2);
    const int r1 = r0 + 8;
#pragma unroll
    for (int nt = 0; nt < 8; nt++) {
        int d = nt * 8 + (lane & 3) * 2;
        if (r0 < S_LEN) {
            float o0 = oacc[nt][0] * inv0, o1 = oacc[nt][1] * inv0;
            size_t off = ((size_t)b * S_LEN + r0) * E_DIM + h * DH + d;
            *(uint32_t*)&g_ahi[off] = pk2h(o0, o1);
            *(uint32_t*)&g_alo[off] = pk2h(o0 - __half2float(__float2half_rn(o0)),
                                           o1 - __half2float(__float2half_rn(o1)));
        }
        if (r1 < S_LEN) {
            float o2 = oacc[nt][2] * inv1, o3 = oacc[nt][3] * inv1;
            size_t off = ((size_t)b * S_LEN + r1) * E_DIM + h * DH + d;
            *(uint32_t*)&g_ahi[off] = pk2h(o2, o3);
            *(uint32_t*)&g_alo[off] = pk2h(o2 - __half2float(__float2half_rn(o2)),
                                           o3 - __half2float(__float2half_rn(o3)));
        }
    }
}

// ======================= launch =============================================
extern "C" void kernel_launch(void* const* d_in, const int* in_sizes, int n_in,
                              void* d_out, int out_size)
{
    (void)in_sizes; (void)n_in; (void)out_size;
    const float* x      = (const float*)d_in[0];
    const float* w_qkv  = (const float*)d_in[1];
    const float* w_proj = (const float*)d_in[2];
    float* out = (float*)d_out;

    void *ahi, *bh, *ph;
    cudaGetSymbolAddress(&ahi, g_ahi);
    cudaGetSymbolAddress(&bh, g_bh);
    cudaGetSymbolAddress(&ph, g_ph);

    cudaFuncSetAttribute((const void*)mma_gemm<true, false>,
                         cudaFuncAttributeMaxDynamicSharedMemorySize, GEMM_SMEM);
    cudaFuncSetAttribute((const void*)mma_gemm<false, true>,
                         cudaFuncAttributeMaxDynamicSharedMemorySize, GEMM_SMEM);
    cudaFuncSetAttribute(flash_mma, cudaFuncAttributeMaxDynamicSharedMemorySize, FLASH_SMEM);

    const int MT = (M_ROWS + 127) / 128;   // 145

    // 1) input conversions up front (x single fp16; weights single fp16)
    {
        int n4 = M_ROWS * E_DIM / 4;
        split1_h<<<(n4 + 255) / 256, 256>>>((const float4*)x, (uint2*)ahi, n4);
        int w4 = QKV_F * E_DIM / 4;
        split1_h<<<(w4 + 255) / 256, 256>>>((const float4*)w_qkv, (uint2*)bh, w4);
        int p4 = E_DIM * E_DIM / 4;
        split1_h<<<(p4 + 255) / 256, 256>>>((const float4*)w_proj, (uint2*)ph, p4);
    }

    // 2) QKV projection (A single fp16) -> q,k,v fp16
    mma_gemm<true, false><<<dim3(QKV_F / 128, MT), 256, GEMM_SMEM>>>(
        nullptr, (const __half*)bh);

    // 3) rope (table) + fp16 prep of q (single), k (single), V^T (single)
    convert_rope_split<<<dim3(10, BH), 256>>>();

    // 4) HMMA flash attention -> ctx as fp16 hi/lo into g_ahi/g_alo
    flash_mma<<<dim3(5, BH), 256, FLASH_SMEM>>>();

    // 5) output projection (A = ctx hi+lo for accuracy)
    mma_gemm<false, true><<<dim3(E_DIM / 128, MT), 256, GEMM_SMEM>>>(
        out, (const __half*)ph);
}

// round 17
// speedup vs baseline: 2.0127x; 1.1350x over previous
#include <cuda_runtime.h>
#include <cuda_fp16.h>
#include <math.h>
#include <stdint.h>

#define B_SZ   32
#define S_LEN  577
#define E_DIM  768
#define NH     12
#define DH     64
#define BH     (B_SZ * NH)         // 384
#define M_ROWS (B_SZ * S_LEN)      // 18464
#define QKV_F  (3 * E_DIM)         // 2304
#define SPAD   640

// Scratch (device globals; allocation-free per harness rules)
__device__ __half g_qpre[(size_t)BH * S_LEN * DH];  // pre-rope q fp16 [bh][s][d]
__device__ __half g_kpre[(size_t)BH * S_LEN * DH];  // pre-rope k fp16
__device__ __half g_vpre[(size_t)BH * S_LEN * DH];  // v fp16
__device__ __half g_ahi[(size_t)M_ROWS * E_DIM];    // A (x fp16, then ctx fp16)
__device__ __half g_bh [(size_t)QKV_F * E_DIM];     // w_qkv fp16
__device__ __half g_ph [(size_t)E_DIM * E_DIM];     // w_proj fp16
// flash operands
__device__ __half g_qh [(size_t)BH * S_LEN * DH];   // roped q fp16
__device__ __half g_kh [(size_t)BH * S_LEN * DH];   // roped k fp16
__device__ __half g_vt [(size_t)BH * DH * SPAD];    // V^T fp16 [bh][d][s]

__device__ __forceinline__ uint32_t smem_to_u32(const void* p) {
    uint32_t a;
    asm("{ .reg .u64 t; cvta.to.shared.u64 t, %1; cvt.u32.u64 %0, t; }" : "=r"(a) : "l"(p));
    return a;
}

// ---- mma.sync helpers (fp16 in, fp32 accum) ----
#define LDSM4(r, addr)                                                         \
    asm volatile("ldmatrix.sync.aligned.m8n8.x4.shared.b16 {%0,%1,%2,%3}, [%4];" \
        : "=r"((r)[0]), "=r"((r)[1]), "=r"((r)[2]), "=r"((r)[3]) : "r"(addr))

#define MMA16816(d, a, b0, b1)                                                 \
    asm volatile("mma.sync.aligned.m16n8k16.row.col.f32.f16.f16.f32 "          \
        "{%0,%1,%2,%3}, {%4,%5,%6,%7}, {%8,%9}, {%0,%1,%2,%3};"                \
        : "+f"((d)[0]), "+f"((d)[1]), "+f"((d)[2]), "+f"((d)[3])               \
        : "r"((a)[0]), "r"((a)[1]), "r"((a)[2]), "r"((a)[3]), "r"(b0), "r"(b1))

// 16B-chunk swizzle for [rows][64 fp16] tiles
#define CH8(row, c) (((row) << 7) + ((((c) ^ ((row) & 7))) << 4))

__device__ __forceinline__ uint32_t pk2h(float f0, float f1) {
    __half2 h = __floats2half2_rn(f0, f1);
    return *(uint32_t*)&h;
}

// ======================= fp16 conversion ====================================
__global__ __launch_bounds__(256) void split1_h(const float4* __restrict__ src,
                                                uint2* __restrict__ dst, int n4)
{
    int i = blockIdx.x * blockDim.x + threadIdx.x;
    if (i >= n4) return;
    float4 v = src[i];
    uint2 o;
    o.x = pk2h(v.x, v.y);
    o.y = pk2h(v.z, v.w);
    dst[i] = o;
}

// ======================= HMMA GEMM (fp16, BK=64, cp.async 3-stage) ==========
// C[M,N] = A[M,768] @ B[N,768]^T, single fp16 operands.
// Stage: A[128][64] 16KB @0, B[128][64] 16KB @16384.
#define GEMM_STAGE 32768
#define GEMM_SMEM  (3 * GEMM_STAGE)

template<bool QKV>
__global__ __launch_bounds__(256, 2) void mma_gemm(float* __restrict__ C,
                                                   const __half* __restrict__ Bh)
{
    extern __shared__ char sm[];
    const int tid  = threadIdx.x;
    const int lane = tid & 31;
    const int wid  = tid >> 5;
    const int wm   = wid & 3;          // 4 warps over M (32 rows each)
    const int wn   = wid >> 2;         // 2 warps over N (64 cols each)
    const int row0 = blockIdx.y * 128;
    const int col0 = blockIdx.x * 128;
    const uint32_t smem = smem_to_u32(sm);

    const int arow[2] = { wm * 32 + 0 * 16 + (lane & 7) + ((lane >> 3) & 1) * 8,
                          wm * 32 + 1 * 16 + (lane & 7) + ((lane >> 3) & 1) * 8 };
    const int achk = lane >> 4;
    const int br   = (lane & 7) + ((lane >> 4) << 3);
    const int bchk = (lane >> 3) & 1;

#define ISSUE(s_)                                                              \
    {                                                                          \
        uint32_t sb_ = smem + ((s_) % 3) * GEMM_STAGE;                         \
        int k0_ = (s_) * 64;                                                   \
        _Pragma("unroll")                                                      \
        for (int it = 0; it < 4; it++) {                                       \
            int idx = tid + it * 256;                                          \
            int r = idx >> 3, c = idx & 7;                                     \
            int rA = row0 + r;                                                 \
            uint32_t szA = (rA < M_ROWS) ? 16u : 0u;                           \
            size_t offA = (size_t)(rA < M_ROWS ? rA : 0) * E_DIM + k0_ + c * 8; \
            size_t offB = (size_t)(col0 + r) * E_DIM + k0_ + c * 8;            \
            uint32_t co = CH8(r, c);                                           \
            asm volatile("cp.async.cg.shared.global [%0], [%1], 16, %2;"       \
                :: "r"(sb_ + co), "l"(g_ahi + offA), "r"(szA));                \
            asm volatile("cp.async.cg.shared.global [%0], [%1], 16;"           \
                :: "r"(sb_ + 16384 + co), "l"(Bh + offB));                     \
        }                                                                      \
        asm volatile("cp.async.commit_group;");                                \
    }

    ISSUE(0)
    ISSUE(1)

    float acc[2][8][4] = {};

    for (int s = 0; s < 12; s++) {
        if (s + 1 < 12) asm volatile("cp.async.wait_group 1;");
        else            asm volatile("cp.async.wait_group 0;");
        __syncthreads();
        if (s + 2 < 12) ISSUE(s + 2)

        const uint32_t sb = smem + (s % 3) * GEMM_STAGE;
#pragma unroll
        for (int kt = 0; kt < 4; kt++) {
            uint32_t af[2][4];
#pragma unroll
            for (int i = 0; i < 2; i++)
                LDSM4(af[i], sb + CH8(arow[i], kt * 2 + achk));
            uint32_t bf[4][4];
#pragma unroll
            for (int g = 0; g < 4; g++)
                LDSM4(bf[g], sb + 16384 + CH8(wn * 64 + g * 16 + br, kt * 2 + bchk));
#pragma unroll
            for (int i = 0; i < 2; i++)
#pragma unroll
                for (int g = 0; g < 4; g++)
#pragma unroll
                    for (int hh = 0; hh < 2; hh++)
                        MMA16816(acc[i][g*2+hh], af[i], bf[g][hh*2], bf[g][hh*2+1]);
        }
    }
#undef ISSUE

#pragma unroll
    for (int i = 0; i < 2; i++)
#pragma unroll
        for (int half = 0; half < 2; half++) {
            int m = row0 + wm * 32 + i * 16 + (lane >> 2) + half * 8;
            if (m >= M_ROWS) continue;
            int bb = 0, sIdx = 0;
            if (QKV) { bb = m / S_LEN; sIdx = m - bb * S_LEN; }
#pragma unroll
            for (int j = 0; j < 8; j++) {
                int n = col0 + wn * 64 + j * 8 + (lane & 3) * 2;
                float2 v = make_float2(acc[i][j][half*2], acc[i][j][half*2+1]);
                if (QKV) {
                    int t = n / E_DIM, r = n - t * E_DIM;
                    int h = r >> 6, d = r & 63;
                    __half* dst = (t == 0) ? g_qpre : (t == 1) ? g_kpre : g_vpre;
                    size_t off = (((size_t)bb * NH + h) * S_LEN + sIdx) * DH + d;
                    *(uint32_t*)&dst[off] = pk2h(v.x, v.y);
                } else {
                    *(float2*)&C[(size_t)m * E_DIM + n] = v;
                }
            }
        }
}

// ======================= convert: rope (table) + fp16 prep ==================
__global__ __launch_bounds__(256) void convert_rope_split()
{
    const int bh    = blockIdx.y;
    const int chunk = blockIdx.x;
    const int s0    = chunk * 64;
    const int tid   = threadIdx.x;
    const int wid   = tid >> 5, lane = tid & 31;
    const unsigned full = 0xffffffffu;

    __shared__ float ct[24][16], st[24][16];
    for (int e = tid; e < 384; e += 256) {
        int v = e >> 4, f = e & 15;
        float dv = expf(-(float)(2 * f) * (9.210340371976184f / 32.0f));
        float a  = (float)v * (1.0f / 23.00000001f) * dv;
        ct[v][f] = cosf(a);
        st[v][f] = sinf(a);
    }
    __syncthreads();

    const int fi = lane >> 1;

#pragma unroll
    for (int t = 0; t < 2; t++) {
        const __half* srcp = t ? g_kpre : g_qpre;
        __half* dstp = t ? g_kh : g_qh;
#pragma unroll
        for (int ps = 0; ps < 8; ps++) {
            int s = s0 + ps * 8 + wid;
            float v0 = 0.f, v1 = 0.f;
            bool valid = (s < S_LEN);
            if (valid) {
                const __half* base = srcp + ((size_t)bh * S_LEN + s) * DH;
                v0 = __half2float(base[lane]);
                v1 = __half2float(base[lane + 32]);
            }
            float p0 = __shfl_sync(full, v0, (lane + 31) & 31);
            float p1 = __shfl_sync(full, v1, (lane + 31) & 31);
            if (valid && s > 0) {
                int p  = s - 1;
                int px = p % 24, py = p / 24;
                v0 = v0 * ct[px][fi] + p0 * st[px][fi];
                v1 = v1 * ct[py][fi] + p1 * st[py][fi];
            }
            if (valid) {
                size_t off = ((size_t)bh * S_LEN + s) * DH;
                dstp[off + lane]      = __float2half_rn(v0);
                dstp[off + lane + 32] = __float2half_rn(v1);
            }
        }
    }

    // V transpose -> g_vt fp16 [bh][d][s0..s0+64) (zeros beyond S_LEN)
    __shared__ float vbuf[64][65];
#pragma unroll
    for (int it = 0; it < 16; it++) {
        int idx = tid + it * 256;
        int r = idx >> 6, c = idx & 63;
        float val = (s0 + r < S_LEN)
            ? __half2float(g_vpre[((size_t)bh * S_LEN + s0 + r) * DH + c]) : 0.f;
        vbuf[c][r] = val;
    }
    __syncthreads();
    {
        int d = tid >> 2, grp = tid & 3;
        __half hh[16];
#pragma unroll
        for (int i = 0; i < 16; i++)
            hh[i] = __float2half_rn(vbuf[d][grp * 16 + i]);
        size_t dst = (size_t)bh * (DH * SPAD) + (size_t)d * SPAD + s0 + grp * 16;
        *(uint4*)(g_vt + dst)     = *(uint4*)hh;
        *(uint4*)(g_vt + dst + 8) = *(uint4*)(hh + 8);
    }
}

// ======================= HMMA flash attention (fp16, 32KB, 2 CTA/SM) ========
#define FLASH_SMEM 32768

__global__ __launch_bounds__(256, 2) void flash_mma()
{
    extern __shared__ char sm[];
    const uint32_t smem = smem_to_u32(sm);

    const int bh  = blockIdx.y;
    const int i0  = blockIdx.x * 128;
    const int tid = threadIdx.x;
    const int lane = tid & 31, wid = tid >> 5;

#define KVBASE(t_) (smem + (((t_) & 1) ? 0u : 16384u))

#define ISSUE_KV(t_)                                                           \
    {                                                                          \
        uint32_t kb_ = KVBASE(t_);                                             \
        int j0_ = (t_) * 64;                                                   \
        _Pragma("unroll")                                                      \
        for (int it = 0; it < 2; it++) {                                       \
            int idx = tid + it * 256;                                          \
            int r = idx >> 3, c = idx & 7;                                     \
            int sj = j0_ + r;                                                  \
            uint32_t szK = (sj < S_LEN) ? 16u : 0u;                            \
            size_t koff = ((size_t)bh * S_LEN + (sj < S_LEN ? sj : 0)) * DH + c * 8; \
            size_t voff = (size_t)bh * (DH * SPAD) + (size_t)r * SPAD + j0_ + c * 8; \
            uint32_t co = CH8(r, c);                                           \
            asm volatile("cp.async.cg.shared.global [%0], [%1], 16, %2;"       \
                :: "r"(kb_ + co), "l"(g_kh + koff), "r"(szK));                 \
            asm volatile("cp.async.cg.shared.global [%0], [%1], 16;"           \
                :: "r"(kb_ + 8192 + co), "l"(g_vt + voff));                    \
        }                                                                      \
        asm volatile("cp.async.commit_group;");                                \
    }

    ISSUE_KV(0)

#pragma unroll
    for (int it = 0; it < 4; it++) {
        int idx = tid + it * 256;
        int r = idx >> 3, c = idx & 7;
        int s = i0 + r;
        uint4 vh = make_uint4(0u,0u,0u,0u);
        if (s < S_LEN)
            vh = *(const uint4*)(g_qh + ((size_t)bh * S_LEN + s) * DH + c * 8);
        *(uint4*)(sm + CH8(r, c)) = vh;
    }
    __syncthreads();

    uint32_t qhf[4][4];
    {
        const int ar = wid * 16 + (lane & 7) + ((lane >> 3) & 1) * 8;
        const int ac = lane >> 4;
#pragma unroll
        for (int kt = 0; kt < 4; kt++)
            LDSM4(qhf[kt], smem + CH8(ar, kt * 2 + ac));
    }
    __syncthreads();

    ISSUE_KV(1)

    float oacc[8][4] = {};
    float m0 = -1e30f, m1 = -1e30f, l0 = 0.f, l1 = 0.f;

    const int br = (lane & 7) + ((lane >> 4) << 3);
    const int bc = (lane >> 3) & 1;

    for (int t = 0; t < 10; t++) {
        const int j0 = t * 64;
        if (t < 8) asm volatile("cp.async.wait_group 1;");
        else       asm volatile("cp.async.wait_group 0;");
        __syncthreads();

        const uint32_t kvb  = KVBASE(t);
        const uint32_t kh32 = kvb, vh32 = kvb + 8192;

        float sacc[8][4] = {};
#pragma unroll
        for (int kt = 0; kt < 4; kt++) {
            uint32_t khf[4][4];
#pragma unroll
            for (int g = 0; g < 4; g++)
                LDSM4(khf[g], kh32 + CH8(g * 16 + br, kt * 2 + bc));
#pragma unroll
            for (int g = 0; g < 4; g++)
#pragma unroll
                for (int hh = 0; hh < 2; hh++)
                    MMA16816(sacc[g*2+hh], qhf[kt], khf[g][hh*2], khf[g][hh*2+1]);
        }

        float tm0 = -1e30f, tm1 = -1e30f;
#pragma unroll
        for (int nt = 0; nt < 8; nt++) {
            int jb = j0 + nt * 8 + (lane & 3) * 2;
            sacc[nt][0] = (jb     < S_LEN) ? sacc[nt][0] * 0.125f : -1e30f;
            sacc[nt][1] = (jb + 1 < S_LEN) ? sacc[nt][1] * 0.125f : -1e30f;
            sacc[nt][2] = (jb     < S_LEN) ? sacc[nt][2] * 0.125f : -1e30f;
            sacc[nt][3] = (jb + 1 < S_LEN) ? sacc[nt][3] * 0.125f : -1e30f;
            tm0 = fmaxf(tm0, fmaxf(sacc[nt][0], sacc[nt][1]));
            tm1 = fmaxf(tm1, fmaxf(sacc[nt][2], sacc[nt][3]));
        }
        tm0 = fmaxf(tm0, __shfl_xor_sync(0xffffffffu, tm0, 1));
        tm0 = fmaxf(tm0, __shfl_xor_sync(0xffffffffu, tm0, 2));
        tm1 = fmaxf(tm1, __shfl_xor_sync(0xffffffffu, tm1, 1));
        tm1 = fmaxf(tm1, __shfl_xor_sync(0xffffffffu, tm1, 2));
        float mn0 = fmaxf(m0, tm0), mn1 = fmaxf(m1, tm1);
        float f0 = __expf(m0 - mn0), f1 = __expf(m1 - mn1);
        m0 = mn0; m1 = mn1;

        float rs0 = 0.f, rs1 = 0.f;
#pragma unroll
        for (int nt = 0; nt < 8; nt++) {
            sacc[nt][0] = __expf(sacc[nt][0] - mn0);
            sacc[nt][1] = __expf(sacc[nt][1] - mn0);
            sacc[nt][2] = __expf(sacc[nt][2] - mn1);
            sacc[nt][3] = __expf(sacc[nt][3] - mn1);
            rs0 += sacc[nt][0] + sacc[nt][1];
            rs1 += sacc[nt][2] + sacc[nt][3];
        }
        rs0 += __shfl_xor_sync(0xffffffffu, rs0, 1);
        rs0 += __shfl_xor_sync(0xffffffffu, rs0, 2);
        rs1 += __shfl_xor_sync(0xffffffffu, rs1, 1);
        rs1 += __shfl_xor_sync(0xffffffffu, rs1, 2);
        l0 = l0 * f0 + rs0;
        l1 = l1 * f1 + rs1;

#pragma unroll
        for (int nt = 0; nt < 8; nt++) {
            oacc[nt][0] *= f0; oacc[nt][1] *= f0;
            oacc[nt][2] *= f1; oacc[nt][3] *= f1;
        }

        uint32_t pahi[4][4], palo[4][4];
#pragma unroll
        for (int kt = 0; kt < 4; kt++) {
            const int t0 = kt * 2, t1 = kt * 2 + 1;
            float v00 = sacc[t0][0], v01 = sacc[t0][1];
            float v02 = sacc[t0][2], v03 = sacc[t0][3];
            float v10 = sacc[t1][0], v11 = sacc[t1][1];
            float v12 = sacc[t1][2], v13 = sacc[t1][3];
            pahi[kt][0] = pk2h(v00, v01);
            pahi[kt][1] = pk2h(v02, v03);
            pahi[kt][2] = pk2h(v10, v11);
            pahi[kt][3] = pk2h(v12, v13);
            palo[kt][0] = pk2h(v00 - __half2float(__float2half_rn(v00)),
                               v01 - __half2float(__float2half_rn(v01)));
            palo[kt][1] = pk2h(v02 - __half2float(__float2half_rn(v02)),
                               v03 - __half2float(__float2half_rn(v03)));
            palo[kt][2] = pk2h(v10 - __half2float(__float2half_rn(v10)),
                               v11 - __half2float(__float2half_rn(v11)));
            palo[kt][3] = pk2h(v12 - __half2float(__float2half_rn(v12)),
                               v13 - __half2float(__float2half_rn(v13)));
        }

#pragma unroll
        for (int kt = 0; kt < 4; kt++) {
            uint32_t vhf[4][4];
#pragma unroll
            for (int g = 0; g < 4; g++)
                LDSM4(vhf[g], vh32 + CH8(g * 16 + br, kt * 2 + bc));
#pragma unroll
            for (int g = 0; g < 4; g++)
#pragma unroll
                for (int hh = 0; hh < 2; hh++)
                    MMA16816(oacc[g*2+hh], pahi[kt], vhf[g][hh*2], vhf[g][hh*2+1]);
#pragma unroll
            for (int g = 0; g < 4; g++)
#pragma unroll
                for (int hh = 0; hh < 2; hh++)
                    MMA16816(oacc[g*2+hh], palo[kt], vhf[g][hh*2], vhf[g][hh*2+1]);
        }
        __syncthreads();
        if (t + 2 < 10) ISSUE_KV(t + 2)
    }
#undef ISSUE_KV
#undef KVBASE

    // epilogue: ctx as single fp16 into g_ahi (A of out-proj GEMM)
    const float inv0 = 1.f / l0, inv1 = 1.f / l1;
    const int b = bh / NH, h = bh % NH;
    const int r0 = i0 + wid * 16 + (lane >> 2);
    const int r1 = r0 + 8;
#pragma unroll
    for (int nt = 0; nt < 8; nt++) {
        int d = nt * 8 + (lane & 3) * 2;
        if (r0 < S_LEN) {
            size_t off = ((size_t)b * S_LEN + r0) * E_DIM + h * DH + d;
            *(uint32_t*)&g_ahi[off] = pk2h(oacc[nt][0] * inv0, oacc[nt][1] * inv0);
        }
        if (r1 < S_LEN) {
            size_t off = ((size_t)b * S_LEN + r1) * E_DIM + h * DH + d;
            *(uint32_t*)&g_ahi[off] = pk2h(oacc[nt][2] * inv1, oacc[nt][3] * inv1);
        }
    }
}

// ======================= launch =============================================
extern "C" void kernel_launch(void* const* d_in, const int* in_sizes, int n_in,
                              void* d_out, int out_size)
{
    (void)in_sizes; (void)n_in; (void)out_size;
    const float* x      = (const float*)d_in[0];
    const float* w_qkv  = (const float*)d_in[1];
    const float* w_proj = (const float*)d_in[2];
    float* out = (float*)d_out;

    void *ahi, *bh, *ph;
    cudaGetSymbolAddress(&ahi, g_ahi);
    cudaGetSymbolAddress(&bh, g_bh);
    cudaGetSymbolAddress(&ph, g_ph);

    cudaFuncSetAttribute(mma_gemm<true>,  cudaFuncAttributeMaxDynamicSharedMemorySize, GEMM_SMEM);
    cudaFuncSetAttribute(mma_gemm<false>, cudaFuncAttributeMaxDynamicSharedMemorySize, GEMM_SMEM);
    cudaFuncSetAttribute(flash_mma, cudaFuncAttributeMaxDynamicSharedMemorySize, FLASH_SMEM);

    const int MT = (M_ROWS + 127) / 128;   // 145

    // 1) input conversions up front
    {
        int n4 = M_ROWS * E_DIM / 4;
        split1_h<<<(n4 + 255) / 256, 256>>>((const float4*)x, (uint2*)ahi, n4);
        int w4 = QKV_F * E_DIM / 4;
        split1_h<<<(w4 + 255) / 256, 256>>>((const float4*)w_qkv, (uint2*)bh, w4);
        int p4 = E_DIM * E_DIM / 4;
        split1_h<<<(p4 + 255) / 256, 256>>>((const float4*)w_proj, (uint2*)ph, p4);
    }

    // 2) QKV projection -> q,k,v fp16
    mma_gemm<true><<<dim3(QKV_F / 128, MT), 256, GEMM_SMEM>>>(
        nullptr, (const __half*)bh);

    // 3) rope (table) + fp16 prep of q, k, V^T
    convert_rope_split<<<dim3(10, BH), 256>>>();

    // 4) HMMA flash attention -> ctx fp16 into g_ahi
    flash_mma<<<dim3(5, BH), 256, FLASH_SMEM>>>();

    // 5) output projection
    mma_gemm<false><<<dim3(E_DIM / 128, MT), 256, GEMM_SMEM>>>(
        out, (const __half*)ph);
}